// round 3
// baseline (speedup 1.0000x reference)
#include <cuda_runtime.h>
#include <math.h>

#define TT   2048
#define DD   2048
#define NQ   16
#define NKV  4
#define HDIM 128
#define NE   16
#define NF   1024
#define TOPK 4

// ---------------- scratch (static device globals; no allocation) ----------------
__device__ float g_hn  [TT * DD];            // rmsnorm1 output
__device__ float g_q   [TT * NQ * HDIM];
__device__ float g_k   [TT * NKV * HDIM];
__device__ float g_v   [TT * NKV * HDIM];
__device__ float g_attn[TT * NQ * HDIM];
__device__ float g_hmid[TT * DD];            // residual + attn_out
__device__ float g_h2  [TT * DD];            // rmsnorm2 output
__device__ float g_gu  [TT * TOPK * 2 * NF]; // gate_up rows (rowid = t*4+slot)
__device__ float g_gated[TT * TOPK * NF];
__device__ float g_rw  [TT * TOPK];          // normalized routing weight per slot
__device__ int   g_ecnt[NE];
__device__ int   g_erows[NE * TT];           // rowids per expert

// ---------------- RMSNorm over D=2048 (one block per row) ----------------
__global__ void rmsnorm_kernel(const float* __restrict__ x,
                               const float* __restrict__ w,
                               float* __restrict__ out)
{
    int t = blockIdx.x;
    const float4* xr = (const float4*)(x + (size_t)t * DD);
    const float4* wr = (const float4*)w;
    float4* orow = (float4*)(out + (size_t)t * DD);
    int tid = threadIdx.x;  // 256 threads, 512 float4 per row
    float4 v0 = xr[tid], v1 = xr[tid + 256];
    float ss = v0.x*v0.x + v0.y*v0.y + v0.z*v0.z + v0.w*v0.w
             + v1.x*v1.x + v1.y*v1.y + v1.z*v1.z + v1.w*v1.w;
#pragma unroll
    for (int o = 16; o; o >>= 1) ss += __shfl_xor_sync(0xffffffffu, ss, o);
    __shared__ float red[8];
    if ((tid & 31) == 0) red[tid >> 5] = ss;
    __syncthreads();
    float tot = red[0]+red[1]+red[2]+red[3]+red[4]+red[5]+red[6]+red[7];
    float r = rsqrtf(tot / (float)DD + 1e-6f);
    float4 w0 = wr[tid], w1 = wr[tid + 256];
    float4 o0, o1;
    o0.x = v0.x*r*w0.x; o0.y = v0.y*r*w0.y; o0.z = v0.z*r*w0.z; o0.w = v0.w*r*w0.w;
    o1.x = v1.x*r*w1.x; o1.y = v1.y*r*w1.y; o1.z = v1.z*r*w1.z; o1.w = v1.w*r*w1.w;
    orow[tid] = o0; orow[tid + 256] = o1;
}

// ---------------- per-head RMSNorm + RoPE (in place on g_q / g_k) ----------------
__global__ void normrope_kernel(const float* __restrict__ cosb,
                                const float* __restrict__ sinb,
                                const float* __restrict__ qnw,
                                const float* __restrict__ knw)
{
    int t = blockIdx.x;
    int head = blockIdx.y;      // 0..15 -> q, 16..19 -> k
    int h = threadIdx.x;        // 128 threads
    float* buf;
    const float* nw;
    if (head < NQ) { buf = g_q + ((size_t)t * NQ + head) * HDIM;        nw = qnw; }
    else           { buf = g_k + ((size_t)t * NKV + (head - NQ)) * HDIM; nw = knw; }
    float v = buf[h];
    float ss = v * v;
#pragma unroll
    for (int o = 16; o; o >>= 1) ss += __shfl_xor_sync(0xffffffffu, ss, o);
    __shared__ float red[4];
    __shared__ float xs[128];
    if ((h & 31) == 0) red[h >> 5] = ss;
    __syncthreads();
    float tot = red[0] + red[1] + red[2] + red[3];
    float xn = v * rsqrtf(tot / (float)HDIM + 1e-6f) * nw[h];
    xs[h] = xn;
    __syncthreads();
    float c = cosb[(size_t)t * HDIM + h];
    float s = sinb[(size_t)t * HDIM + h];
    float other = (h < 64) ? xs[h + 64] : xs[h - 64];
    buf[h] = (h < 64) ? (xn * c - other * s) : (xn * c + other * s);
}

// ---------------- shared GEMM mainloop: 128x128 tile, BK=16, 8x8 micro ----------------
__device__ __forceinline__ void gemm_tiles(const float* __restrict__ Arow, // this thread's A row base (or null)
                                           const float* __restrict__ B,
                                           int K, int ldb, int n0,
                                           float (*As)[128], float (*Bs)[128],
                                           float acc[8][8])
{
    int tid = threadIdx.x;
    int tx = tid & 15, ty = tid >> 4;
    int am = tid >> 1;            // A tile-local row this thread loads
    int ak = (tid & 1) * 8;       // k base within 16
    const float* bptr = B + (size_t)(tid >> 4) * ldb + n0 + (size_t)(tid & 15) * 8;

    for (int k0 = 0; k0 < K; k0 += 16) {
        float4 a0, a1;
        if (Arow) {
            a0 = *(const float4*)(Arow + k0 + ak);
            a1 = *(const float4*)(Arow + k0 + ak + 4);
        } else {
            a0 = make_float4(0.f, 0.f, 0.f, 0.f); a1 = a0;
        }
        float4 b0 = *(const float4*)(bptr + (size_t)k0 * ldb);
        float4 b1 = *(const float4*)(bptr + (size_t)k0 * ldb + 4);
        __syncthreads();   // previous compute done before overwriting smem
        As[ak + 0][am] = a0.x; As[ak + 1][am] = a0.y;
        As[ak + 2][am] = a0.z; As[ak + 3][am] = a0.w;
        As[ak + 4][am] = a1.x; As[ak + 5][am] = a1.y;
        As[ak + 6][am] = a1.z; As[ak + 7][am] = a1.w;
        *(float4*)&Bs[tid >> 4][(tid & 15) * 8]     = b0;
        *(float4*)&Bs[tid >> 4][(tid & 15) * 8 + 4] = b1;
        __syncthreads();
#pragma unroll
        for (int kk = 0; kk < 16; kk++) {
            float4 aa0 = *(float4*)&As[kk][ty * 8];
            float4 aa1 = *(float4*)&As[kk][ty * 8 + 4];
            float4 bb0 = *(float4*)&Bs[kk][tx * 8];
            float4 bb1 = *(float4*)&Bs[kk][tx * 8 + 4];
            float af[8] = {aa0.x, aa0.y, aa0.z, aa0.w, aa1.x, aa1.y, aa1.z, aa1.w};
            float bf[8] = {bb0.x, bb0.y, bb0.z, bb0.w, bb1.x, bb1.y, bb1.z, bb1.w};
#pragma unroll
            for (int i = 0; i < 8; i++)
#pragma unroll
                for (int j = 0; j < 8; j++)
                    acc[i][j] += af[i] * bf[j];
        }
    }
}

// Plain C = A@B (+ optional elementwise addend). M,N multiples of 128, K of 16.
__global__ void __launch_bounds__(256) sgemm_kernel(const float* __restrict__ A,
                                                    const float* __restrict__ B,
                                                    float* __restrict__ C,
                                                    const float* __restrict__ addsrc,
                                                    int M, int N, int K)
{
    __shared__ float As[16][128];
    __shared__ float Bs[16][128];
    int n0 = blockIdx.x * 128, m0 = blockIdx.y * 128;
    float acc[8][8] = {};
    const float* Arow = A + (size_t)(m0 + (threadIdx.x >> 1)) * K;
    gemm_tiles(Arow, B, K, N, n0, As, Bs, acc);
    int tx = threadIdx.x & 15, ty = threadIdx.x >> 4;
#pragma unroll
    for (int i = 0; i < 8; i++) {
        size_t r = (size_t)(m0 + ty * 8 + i);
        float* crow = C + r * N + n0 + tx * 8;
        if (addsrc) {
            const float* arow = addsrc + r * N + n0 + tx * 8;
#pragma unroll
            for (int j = 0; j < 8; j++) crow[j] = acc[i][j] + arow[j];
        } else {
#pragma unroll
            for (int j = 0; j < 8; j++) crow[j] = acc[i][j];
        }
    }
}

// ---------------- flash attention: 64-row query tiles, online softmax ----------------
// block = 256 threads = 64 rows x 4 lanes; lane L owns head dims {L, L+4, ..., L+124}
#define ATTN_SMEM_FLOATS (64*128 + 64*128 + 64*65)
__global__ void __launch_bounds__(256) attn_kernel()
{
    extern __shared__ float sm[];
    float* Ks = sm;
    float* Vs = sm + 64 * 128;
    float* Ss = sm + 2 * 64 * 128;   // [64][65] padded
    int m0 = blockIdx.x * 64;
    int head = blockIdx.y;
    int kvh = head >> 2;
    int tid = threadIdx.x;
    int row = tid >> 2;
    int lane4 = tid & 3;
    int tglob = m0 + row;
    const float scale = 0.08838834764831843f;  // 1/sqrt(128)

    float qreg[32];
    const float* qrow = g_q + ((size_t)tglob * NQ + head) * HDIM;
#pragma unroll
    for (int i = 0; i < 32; i++) qreg[i] = qrow[4 * i + lane4];

    float acc[32];
#pragma unroll
    for (int i = 0; i < 32; i++) acc[i] = 0.f;
    float m_i = -1e30f, l_i = 0.f;

    int jend = m0 + 64;
    for (int j0 = 0; j0 < jend; j0 += 64) {
        // stage K and V tiles (64x128 each)
#pragma unroll
        for (int i = 0; i < 8; i++) {
            int idx = tid + 256 * i;        // float4 index, 2048 total
            int r = idx >> 5, c4 = idx & 31;
            size_t gsrc = ((size_t)(j0 + r) * NKV + kvh) * HDIM + c4 * 4;
            *(float4*)&Ks[r * 128 + c4 * 4] = *(const float4*)(g_k + gsrc);
            *(float4*)&Vs[r * 128 + c4 * 4] = *(const float4*)(g_v + gsrc);
        }
        __syncthreads();

        float tmax = -1e30f;
#pragma unroll 4
        for (int j = 0; j < 64; j++) {
            const float* kr = Ks + j * 128;
            float p = 0.f;
#pragma unroll
            for (int i = 0; i < 32; i++) p += qreg[i] * kr[4 * i + lane4];
            p += __shfl_xor_sync(0xffffffffu, p, 1);
            p += __shfl_xor_sync(0xffffffffu, p, 2);
            float s = p * scale + ((j0 + j <= tglob) ? 0.f : -1e9f);
            tmax = fmaxf(tmax, s);
            if ((j & 3) == lane4) Ss[row * 65 + j] = s;
        }
        __syncwarp();

        float m_new = fmaxf(m_i, tmax);
        float corr = __expf(m_i - m_new);
        l_i *= corr;
#pragma unroll
        for (int i = 0; i < 32; i++) acc[i] *= corr;

#pragma unroll 4
        for (int j = 0; j < 64; j++) {
            float pj = __expf(Ss[row * 65 + j] - m_new);
            l_i += pj;
            const float* vr = Vs + j * 128;
#pragma unroll
            for (int i = 0; i < 32; i++) acc[i] += pj * vr[4 * i + lane4];
        }
        m_i = m_new;
        __syncthreads();
    }

    float inv = 1.f / l_i;
    float* orow = g_attn + ((size_t)tglob * NQ + head) * HDIM;
#pragma unroll
    for (int i = 0; i < 32; i++) orow[4 * i + lane4] = acc[i] * inv;
}

// ---------------- routing ----------------
__global__ void zero_cnt_kernel() { if (threadIdx.x < NE) g_ecnt[threadIdx.x] = 0; }

__global__ void route_kernel(const float* __restrict__ gate_w)
{
    int t = blockIdx.x;
    int tid = threadIdx.x;   // 128
    const float* x = g_h2 + (size_t)t * DD;
    float acc[NE];
#pragma unroll
    for (int e = 0; e < NE; e++) acc[e] = 0.f;
    for (int d = tid; d < DD; d += 128) {
        float xv = x[d];
        const float* gw = gate_w + (size_t)d * NE;
#pragma unroll
        for (int e = 0; e < NE; e++) acc[e] += xv * gw[e];
    }
    __shared__ float s[NE * 128];
#pragma unroll
    for (int e = 0; e < NE; e++) s[e * 128 + tid] = acc[e];
    __syncthreads();
    __shared__ float logits[NE];
    if (tid < NE) {
        float sum = 0.f;
        for (int i = 0; i < 128; i++) sum += s[tid * 128 + i];
        logits[tid] = sum;
    }
    __syncthreads();
    if (tid == 0) {
        float mx = -1e30f;
        for (int e = 0; e < NE; e++) mx = fmaxf(mx, logits[e]);
        float p[NE], Z = 0.f;
        for (int e = 0; e < NE; e++) { p[e] = expf(logits[e] - mx); Z += p[e]; }
        for (int e = 0; e < NE; e++) p[e] /= Z;
        int idx[TOPK]; float val[TOPK]; bool used[NE] = {};
        float wsum = 0.f;
        for (int k = 0; k < TOPK; k++) {
            int best = -1; float bv = -1.f;
            for (int e = 0; e < NE; e++)
                if (!used[e] && p[e] > bv) { bv = p[e]; best = e; }
            used[best] = true; idx[k] = best; val[k] = bv; wsum += bv;
        }
        for (int k = 0; k < TOPK; k++) {
            int rowid = t * TOPK + k;
            g_rw[rowid] = val[k] / wsum;
            int e = idx[k];
            int pos = atomicAdd(&g_ecnt[e], 1);
            g_erows[e * TT + pos] = rowid;
        }
    }
}

// ---------------- MoE expert GEMMs ----------------
__global__ void __launch_bounds__(256) moe_gemm1_kernel(const float* __restrict__ gup_w)
{
    __shared__ float As[16][128];
    __shared__ float Bs[16][128];
    int e = blockIdx.z;
    int cnt = g_ecnt[e];
    int m0 = blockIdx.y * 128;
    if (m0 >= cnt) return;
    int n0 = blockIdx.x * 128;
    const float* B = gup_w + (size_t)e * DD * (2 * NF);
    int mr = m0 + (threadIdx.x >> 1);
    const float* Arow = nullptr;
    if (mr < cnt) Arow = g_h2 + (size_t)(g_erows[e * TT + mr] >> 2) * DD;
    float acc[8][8] = {};
    gemm_tiles(Arow, B, DD, 2 * NF, n0, As, Bs, acc);
    int tx = threadIdx.x & 15, ty = threadIdx.x >> 4;
#pragma unroll
    for (int i = 0; i < 8; i++) {
        int r = m0 + ty * 8 + i;
        if (r < cnt) {
            int rowid = g_erows[e * TT + r];
            float* crow = g_gu + (size_t)rowid * (2 * NF) + n0 + tx * 8;
#pragma unroll
            for (int j = 0; j < 8; j++) crow[j] = acc[i][j];
        }
    }
}

__global__ void silu_kernel()
{
    size_t i = (size_t)blockIdx.x * 256 + threadIdx.x;  // over 8192*1024
    int r = (int)(i >> 10);
    int f = (int)(i & 1023);
    float g = g_gu[(size_t)r * (2 * NF) + f];
    float u = g_gu[(size_t)r * (2 * NF) + NF + f];
    g_gated[i] = u * (g / (1.f + __expf(-g)));
}

__global__ void __launch_bounds__(256) moe_gemm2_kernel(const float* __restrict__ down_w,
                                                        float* __restrict__ out)
{
    __shared__ float As[16][128];
    __shared__ float Bs[16][128];
    int e = blockIdx.z;
    int cnt = g_ecnt[e];
    int m0 = blockIdx.y * 128;
    if (m0 >= cnt) return;
    int n0 = blockIdx.x * 128;
    const float* B = down_w + (size_t)e * NF * DD;
    int mr = m0 + (threadIdx.x >> 1);
    const float* Arow = nullptr;
    if (mr < cnt) Arow = g_gated + (size_t)g_erows[e * TT + mr] * NF;
    float acc[8][8] = {};
    gemm_tiles(Arow, B, NF, DD, n0, As, Bs, acc);
    int tx = threadIdx.x & 15, ty = threadIdx.x >> 4;
#pragma unroll
    for (int i = 0; i < 8; i++) {
        int r = m0 + ty * 8 + i;
        if (r < cnt) {
            int rowid = g_erows[e * TT + r];
            int tok = rowid >> 2;
            float w = g_rw[rowid];
            float* crow = out + (size_t)tok * DD + n0 + tx * 8;
#pragma unroll
            for (int j = 0; j < 8; j++) atomicAdd(&crow[j], w * acc[i][j]);
        }
    }
}

__global__ void copy_out_kernel(float* __restrict__ out)
{
    size_t i = (size_t)blockIdx.x * 256 + threadIdx.x;
    ((float4*)out)[i] = ((const float4*)g_hmid)[i];
}

// ---------------- launch ----------------
extern "C" void kernel_launch(void* const* d_in, const int* in_sizes, int n_in,
                              void* d_out, int out_size)
{
    const float* hidden  = (const float*)d_in[0];
    const float* cosb    = (const float*)d_in[1];
    const float* sinb    = (const float*)d_in[2];
    // d_in[3] attention_mask: equivalent to causal mask, applied analytically
    const float* in_ln   = (const float*)d_in[4];
    const float* post_ln = (const float*)d_in[5];
    const float* q_w     = (const float*)d_in[6];
    const float* k_w     = (const float*)d_in[7];
    const float* v_w     = (const float*)d_in[8];
    const float* o_w     = (const float*)d_in[9];
    const float* q_nw    = (const float*)d_in[10];
    const float* k_nw    = (const float*)d_in[11];
    const float* gate_w  = (const float*)d_in[12];
    const float* gup_w   = (const float*)d_in[13];
    const float* down_w  = (const float*)d_in[14];
    float* out = (float*)d_out;

    float *hn, *q, *k, *v, *attn, *hmid, *h2;
    cudaGetSymbolAddress((void**)&hn,   g_hn);
    cudaGetSymbolAddress((void**)&q,    g_q);
    cudaGetSymbolAddress((void**)&k,    g_k);
    cudaGetSymbolAddress((void**)&v,    g_v);
    cudaGetSymbolAddress((void**)&attn, g_attn);
    cudaGetSymbolAddress((void**)&hmid, g_hmid);
    cudaGetSymbolAddress((void**)&h2,   g_h2);

    const int ATTN_SMEM = ATTN_SMEM_FLOATS * (int)sizeof(float);
    cudaFuncSetAttribute(attn_kernel, cudaFuncAttributeMaxDynamicSharedMemorySize, ATTN_SMEM);

    // 1. pre-attn rmsnorm
    rmsnorm_kernel<<<TT, 256>>>(hidden, in_ln, hn);
    // 2. QKV projections
    sgemm_kernel<<<dim3(16, 16), 256>>>(hn, q_w, q, nullptr, TT, NQ * HDIM, DD);
    sgemm_kernel<<<dim3(4, 16),  256>>>(hn, k_w, k, nullptr, TT, NKV * HDIM, DD);
    sgemm_kernel<<<dim3(4, 16),  256>>>(hn, v_w, v, nullptr, TT, NKV * HDIM, DD);
    // 3. per-head norm + rope
    normrope_kernel<<<dim3(TT, NQ + NKV), 128>>>(cosb, sinb, q_nw, k_nw);
    // 4. attention
    attn_kernel<<<dim3(TT / 64, NQ), 256, ATTN_SMEM>>>();
    // 5. O projection + residual
    sgemm_kernel<<<dim3(16, 16), 256>>>(attn, o_w, hmid, hidden, TT, DD, NQ * HDIM);
    // 6. post-attn rmsnorm
    rmsnorm_kernel<<<TT, 256>>>(hmid, post_ln, h2);
    // 7. routing
    zero_cnt_kernel<<<1, 32>>>();
    route_kernel<<<TT, 128>>>(gate_w);
    // 8. init output with residual, then sparse expert GEMMs scatter-add into it
    copy_out_kernel<<<TT * DD / 4 / 256, 256>>>(out);
    moe_gemm1_kernel<<<dim3(16, 16, NE), 256>>>(gup_w);
    silu_kernel<<<(TT * TOPK * NF) / 256, 256>>>();
    moe_gemm2_kernel<<<dim3(16, 16, NE), 256>>>(down_w, out);
}

// round 5
// speedup vs baseline: 1.5297x; 1.5297x over previous
#include <cuda_runtime.h>
#include <cuda_bf16.h>
#include <math.h>
#include <stdint.h>

#define TT   2048
#define DD   2048
#define NQ   16
#define NKV  4
#define HDIM 128
#define NE   16
#define NF   1024
#define TOPK 4

#define QKVW 3072          // fused qkv width: q 0..2047, k 2048..2559, v 2560..3071
#define KOFF 2048
#define VOFF 2560

// ---------------- scratch (static device globals; no allocation) ----------------
__device__ float g_hn   [TT * DD];
__device__ float g_qkv  [TT * QKVW];
__device__ float g_attn [TT * NQ * HDIM];
__device__ float g_hmid [TT * DD];
__device__ float g_h2   [TT * DD];
__device__ float g_gu   [TT * TOPK * 2 * NF];
__device__ float g_gated[TT * TOPK * NF];
__device__ float g_rw   [TT * TOPK];
__device__ int   g_ecnt [NE];
__device__ int   g_erows[NE * TT];

// transposed + split-bf16 weights  (layout: [N rows][K], K contiguous)
__device__ __nv_bfloat16 g_qkvT_h[QKVW * DD];
__device__ __nv_bfloat16 g_qkvT_l[QKVW * DD];
__device__ __nv_bfloat16 g_owT_h [DD * DD];
__device__ __nv_bfloat16 g_owT_l [DD * DD];
__device__ __nv_bfloat16 g_guT_h [NE * (2 * NF) * DD];
__device__ __nv_bfloat16 g_guT_l [NE * (2 * NF) * DD];
__device__ __nv_bfloat16 g_dwT_h [NE * DD * NF];
__device__ __nv_bfloat16 g_dwT_l [NE * DD * NF];

// ================= helpers =================
__device__ __forceinline__ uint32_t smem_u32(const void* p) {
    uint32_t r;
    asm("{ .reg .u64 t; cvta.to.shared.u64 t, %1; cvt.u32.u64 %0, t; }" : "=r"(r) : "l"(p));
    return r;
}
__device__ __forceinline__ uint32_t pack2bf(__nv_bfloat16 a, __nv_bfloat16 b) {
    return (uint32_t)__bfloat16_as_ushort(a) | ((uint32_t)__bfloat16_as_ushort(b) << 16);
}
__device__ __forceinline__ void ldsm4(uint32_t* r, uint32_t a) {
    asm volatile("ldmatrix.sync.aligned.m8n8.x4.shared.b16 {%0,%1,%2,%3}, [%4];"
                 : "=r"(r[0]), "=r"(r[1]), "=r"(r[2]), "=r"(r[3]) : "r"(a));
}
__device__ __forceinline__ void mma16816(float* c, const uint32_t* a, const uint32_t* b) {
    asm volatile("mma.sync.aligned.m16n8k16.row.col.f32.bf16.bf16.f32 "
                 "{%0,%1,%2,%3}, {%4,%5,%6,%7}, {%8,%9}, {%0,%1,%2,%3};"
                 : "+f"(c[0]), "+f"(c[1]), "+f"(c[2]), "+f"(c[3])
                 : "r"(a[0]), "r"(a[1]), "r"(a[2]), "r"(a[3]), "r"(b[0]), "r"(b[1]));
}

// ================= transpose + split-convert: in[K,N] -> hi/lo [N,K] =================
__global__ void tconv_kernel(const float* __restrict__ in,
                             __nv_bfloat16* __restrict__ oh,
                             __nv_bfloat16* __restrict__ ol,
                             int K, int N)
{
    __shared__ float t[32][33];
    int n0 = blockIdx.x * 32, k0 = blockIdx.y * 32;
    size_t ib = (size_t)blockIdx.z * K * N;
    int tx = threadIdx.x, ty = threadIdx.y;
#pragma unroll
    for (int j = 0; j < 32; j += 8)
        t[ty + j][tx] = in[ib + (size_t)(k0 + ty + j) * N + n0 + tx];
    __syncthreads();
#pragma unroll
    for (int j = 0; j < 32; j += 8) {
        float v = t[tx][ty + j];
        __nv_bfloat16 h = __float2bfloat16(v);
        size_t o = ib + (size_t)(n0 + ty + j) * K + k0 + tx;
        oh[o] = h;
        ol[o] = __float2bfloat16(v - __bfloat162float(h));
    }
}

// ================= HMMA split-bf16 GEMM =================
// Tile 128x128, K-chunk 32, 8 warps (2M x 4N), warp tile 64x32, 3-pass split-bf16.
// mode 0: dense  C[M,N] = A @ B^T (+addsrc)
// mode 1: moe gate_up: A rows = g_h2[erows>>2], C rows = C[erows] (C = g_gu)
// mode 2: moe down: A rows = g_gated[erows], atomicAdd into C[tok] * g_rw
#define AH_OFF 0
#define AL_OFF 10240
#define BH_OFF 20480
#define BL_OFF 30720
#define ER_OFF 40960
#define HM_SMEM (40960 + 512)

__global__ void __launch_bounds__(256) hmma_gemm_kernel(
    int mode, const float* __restrict__ A,
    const __nv_bfloat16* __restrict__ Bh, const __nv_bfloat16* __restrict__ Bl,
    float* __restrict__ C, const float* __restrict__ addsrc, int N, int K)
{
    int e  = blockIdx.z;
    int m0 = blockIdx.y * 128;
    int n0 = blockIdx.x * 128;
    int cnt = 0;
    if (mode != 0) {
        cnt = g_ecnt[e];
        if (m0 >= cnt) return;
        Bh += (size_t)e * N * K;
        Bl += (size_t)e * N * K;
    }

    extern __shared__ char sm[];
    uint32_t sb = smem_u32(sm);
    int tid = threadIdx.x, wid = tid >> 5, lid = tid & 31;
    int* erows_s = (int*)(sm + ER_OFF);
    if (mode != 0 && tid < 128)
        erows_s[tid] = (m0 + tid < cnt) ? g_erows[e * TT + m0 + tid] : 0;
    __syncthreads();

    // per-thread staging: row = tid>>1 (128 rows), half = tid&1 (16 of 32 k)
    int arow = tid >> 1, apart = tid & 1;
    const float* aptr;
    if (mode == 0)      aptr = A + (size_t)(m0 + arow) * K + apart * 16;
    else if (mode == 1) aptr = g_h2 + (size_t)(erows_s[arow] >> 2) * DD + apart * 16;
    else                aptr = g_gated + (size_t)erows_s[arow] * NF + apart * 16;
    const __nv_bfloat16* bhp = Bh + (size_t)(n0 + arow) * K + apart * 16;
    const __nv_bfloat16* blp = Bl + (size_t)(n0 + arow) * K + apart * 16;

    char* ah_st = sm + AH_OFF + arow * 80 + apart * 32;
    char* al_st = sm + AL_OFF + arow * 80 + apart * 32;
    char* bh_st = sm + BH_OFF + arow * 80 + apart * 32;
    char* bl_st = sm + BL_OFF + arow * 80 + apart * 32;

    int wm = wid >> 2, wn = wid & 3;
    int a_r = (lid & 7) + ((lid >> 3) & 1) * 8, a_c = (lid >> 4) * 8;
    int b_r = (lid & 7) + (lid >> 4) * 8,       b_c = ((lid >> 3) & 1) * 8;
    uint32_t a_hi = sb + AH_OFF + (wm * 64 + a_r) * 80 + a_c * 2;
    uint32_t a_lo = a_hi + (AL_OFF - AH_OFF);
    uint32_t b_hi = sb + BH_OFF + (wn * 32 + b_r) * 80 + b_c * 2;
    uint32_t b_lo = b_hi + (BL_OFF - BH_OFF);

    float acc[4][4][4];
#pragma unroll
    for (int mi = 0; mi < 4; mi++)
#pragma unroll
        for (int ni = 0; ni < 4; ni++)
#pragma unroll
            for (int j = 0; j < 4; j++) acc[mi][ni][j] = 0.f;

    int NC = K / 32;
    float4 av[4];
    uint4 bhv[2], blv[2];
#pragma unroll
    for (int i = 0; i < 4; i++) av[i] = *(const float4*)(aptr + i * 4);
    bhv[0] = *(const uint4*)(bhp);     bhv[1] = *(const uint4*)(bhp + 8);
    blv[0] = *(const uint4*)(blp);     blv[1] = *(const uint4*)(blp + 8);

    for (int c = 0; c < NC; c++) {
        __syncthreads();   // previous compute done before overwriting smem
        uint32_t hh[8], ll[8];
#pragma unroll
        for (int i = 0; i < 4; i++) {
            float4 v = av[i];
            __nv_bfloat16 h0 = __float2bfloat16(v.x), h1 = __float2bfloat16(v.y);
            __nv_bfloat16 h2 = __float2bfloat16(v.z), h3 = __float2bfloat16(v.w);
            __nv_bfloat16 l0 = __float2bfloat16(v.x - __bfloat162float(h0));
            __nv_bfloat16 l1 = __float2bfloat16(v.y - __bfloat162float(h1));
            __nv_bfloat16 l2 = __float2bfloat16(v.z - __bfloat162float(h2));
            __nv_bfloat16 l3 = __float2bfloat16(v.w - __bfloat162float(h3));
            hh[2 * i] = pack2bf(h0, h1); hh[2 * i + 1] = pack2bf(h2, h3);
            ll[2 * i] = pack2bf(l0, l1); ll[2 * i + 1] = pack2bf(l2, l3);
        }
        *(uint4*)ah_st        = make_uint4(hh[0], hh[1], hh[2], hh[3]);
        *(uint4*)(ah_st + 16) = make_uint4(hh[4], hh[5], hh[6], hh[7]);
        *(uint4*)al_st        = make_uint4(ll[0], ll[1], ll[2], ll[3]);
        *(uint4*)(al_st + 16) = make_uint4(ll[4], ll[5], ll[6], ll[7]);
        *(uint4*)bh_st        = bhv[0];
        *(uint4*)(bh_st + 16) = bhv[1];
        *(uint4*)bl_st        = blv[0];
        *(uint4*)(bl_st + 16) = blv[1];
        __syncthreads();

        if (c + 1 < NC) {   // prefetch next chunk, overlaps MMA below
            int k0 = (c + 1) * 32;
#pragma unroll
            for (int i = 0; i < 4; i++) av[i] = *(const float4*)(aptr + k0 + i * 4);
            bhv[0] = *(const uint4*)(bhp + k0); bhv[1] = *(const uint4*)(bhp + k0 + 8);
            blv[0] = *(const uint4*)(blp + k0); blv[1] = *(const uint4*)(blp + k0 + 8);
        }

#pragma unroll
        for (int kk = 0; kk < 2; kk++) {
            uint32_t bf_h[8], bf_l[8];
            ldsm4(bf_h,     b_hi + kk * 32);
            ldsm4(bf_h + 4, b_hi + 1280 + kk * 32);
            ldsm4(bf_l,     b_lo + kk * 32);
            ldsm4(bf_l + 4, b_lo + 1280 + kk * 32);
#pragma unroll
            for (int mi = 0; mi < 4; mi++) {
                uint32_t ah[4], al[4];
                ldsm4(ah, a_hi + mi * 1280 + kk * 32);
                ldsm4(al, a_lo + mi * 1280 + kk * 32);
#pragma unroll
                for (int ni = 0; ni < 4; ni++) {
                    mma16816(acc[mi][ni], ah, bf_h + ni * 2);
                    mma16816(acc[mi][ni], ah, bf_l + ni * 2);
                    mma16816(acc[mi][ni], al, bf_h + ni * 2);
                }
            }
        }
    }

    // epilogue
    int g = lid >> 2, tig = lid & 3;
#pragma unroll
    for (int mi = 0; mi < 4; mi++) {
        int r0 = wm * 64 + mi * 16 + g;
        int r1 = r0 + 8;
        bool v0 = true, v1 = true;
        size_t ro0 = 0, ro1 = 0;
        float w0 = 0.f, w1 = 0.f;
        if (mode == 0) {
            ro0 = (size_t)(m0 + r0) * N;
            ro1 = (size_t)(m0 + r1) * N;
        } else {
            v0 = (m0 + r0) < cnt;
            v1 = (m0 + r1) < cnt;
            int rowid0 = erows_s[r0], rowid1 = erows_s[r1];
            if (mode == 1) {
                ro0 = (size_t)rowid0 * (2 * NF);
                ro1 = (size_t)rowid1 * (2 * NF);
            } else {
                ro0 = (size_t)(rowid0 >> 2) * DD;
                ro1 = (size_t)(rowid1 >> 2) * DD;
                if (v0) w0 = g_rw[rowid0];
                if (v1) w1 = g_rw[rowid1];
            }
        }
#pragma unroll
        for (int ni = 0; ni < 4; ni++) {
            int cc = n0 + wn * 32 + ni * 8 + tig * 2;
            float* a = acc[mi][ni];
            if (mode == 0) {
                if (addsrc) {
                    float2 s0 = *(const float2*)(addsrc + ro0 + cc);
                    float2 s1 = *(const float2*)(addsrc + ro1 + cc);
                    *(float2*)(C + ro0 + cc) = make_float2(a[0] + s0.x, a[1] + s0.y);
                    *(float2*)(C + ro1 + cc) = make_float2(a[2] + s1.x, a[3] + s1.y);
                } else {
                    *(float2*)(C + ro0 + cc) = make_float2(a[0], a[1]);
                    *(float2*)(C + ro1 + cc) = make_float2(a[2], a[3]);
                }
            } else if (mode == 1) {
                if (v0) *(float2*)(C + ro0 + cc) = make_float2(a[0], a[1]);
                if (v1) *(float2*)(C + ro1 + cc) = make_float2(a[2], a[3]);
            } else {
                if (v0) { atomicAdd(C + ro0 + cc, w0 * a[0]); atomicAdd(C + ro0 + cc + 1, w0 * a[1]); }
                if (v1) { atomicAdd(C + ro1 + cc, w1 * a[2]); atomicAdd(C + ro1 + cc + 1, w1 * a[3]); }
            }
        }
    }
}

// ================= RMSNorm over D=2048 =================
__global__ void rmsnorm_kernel(const float* __restrict__ x,
                               const float* __restrict__ w,
                               float* __restrict__ out)
{
    int t = blockIdx.x;
    const float4* xr = (const float4*)(x + (size_t)t * DD);
    const float4* wr = (const float4*)w;
    float4* orow = (float4*)(out + (size_t)t * DD);
    int tid = threadIdx.x;
    float4 v0 = xr[tid], v1 = xr[tid + 256];
    float ss = v0.x*v0.x + v0.y*v0.y + v0.z*v0.z + v0.w*v0.w
             + v1.x*v1.x + v1.y*v1.y + v1.z*v1.z + v1.w*v1.w;
#pragma unroll
    for (int o = 16; o; o >>= 1) ss += __shfl_xor_sync(0xffffffffu, ss, o);
    __shared__ float red[8];
    if ((tid & 31) == 0) red[tid >> 5] = ss;
    __syncthreads();
    float tot = red[0]+red[1]+red[2]+red[3]+red[4]+red[5]+red[6]+red[7];
    float r = rsqrtf(tot / (float)DD + 1e-6f);
    float4 w0 = wr[tid], w1 = wr[tid + 256];
    float4 o0, o1;
    o0.x = v0.x*r*w0.x; o0.y = v0.y*r*w0.y; o0.z = v0.z*r*w0.z; o0.w = v0.w*r*w0.w;
    o1.x = v1.x*r*w1.x; o1.y = v1.y*r*w1.y; o1.z = v1.z*r*w1.z; o1.w = v1.w*r*w1.w;
    orow[tid] = o0; orow[tid + 256] = o1;
}

// ================= per-head RMSNorm + RoPE (in place on g_qkv) =================
__global__ void normrope_kernel(const float* __restrict__ cosb,
                                const float* __restrict__ sinb,
                                const float* __restrict__ qnw,
                                const float* __restrict__ knw)
{
    int t = blockIdx.x;
    int head = blockIdx.y;      // 0..15 q, 16..19 k
    int h = threadIdx.x;
    float* buf;
    const float* nw;
    if (head < NQ) { buf = g_qkv + (size_t)t * QKVW + head * HDIM;               nw = qnw; }
    else           { buf = g_qkv + (size_t)t * QKVW + KOFF + (head - NQ) * HDIM; nw = knw; }
    float v = buf[h];
    float ss = v * v;
#pragma unroll
    for (int o = 16; o; o >>= 1) ss += __shfl_xor_sync(0xffffffffu, ss, o);
    __shared__ float red[4];
    __shared__ float xs[128];
    if ((h & 31) == 0) red[h >> 5] = ss;
    __syncthreads();
    float tot = red[0] + red[1] + red[2] + red[3];
    float xn = v * rsqrtf(tot / (float)HDIM + 1e-6f) * nw[h];
    xs[h] = xn;
    __syncthreads();
    float c = cosb[(size_t)t * HDIM + h];
    float s = sinb[(size_t)t * HDIM + h];
    float other = (h < 64) ? xs[h + 64] : xs[h - 64];
    buf[h] = (h < 64) ? (xn * c - other * s) : (xn * c + other * s);
}

// ================= flash attention =================
#define ATTN_SMEM_FLOATS (64*128 + 64*128 + 64*65)
__global__ void __launch_bounds__(256) attn_kernel()
{
    extern __shared__ float smf[];
    float* Ks = smf;
    float* Vs = smf + 64 * 128;
    float* Ss = smf + 2 * 64 * 128;
    int m0 = blockIdx.x * 64;
    int head = blockIdx.y;
    int kvh = head >> 2;
    int tid = threadIdx.x;
    int row = tid >> 2;
    int lane4 = tid & 3;
    int tglob = m0 + row;
    const float scale = 0.08838834764831843f;

    float qreg[32];
    const float* qrow = g_qkv + (size_t)tglob * QKVW + head * HDIM;
#pragma unroll
    for (int i = 0; i < 32; i++) qreg[i] = qrow[4 * i + lane4];

    float acc[32];
#pragma unroll
    for (int i = 0; i < 32; i++) acc[i] = 0.f;
    float m_i = -1e30f, l_i = 0.f;

    int jend = m0 + 64;
    for (int j0 = 0; j0 < jend; j0 += 64) {
#pragma unroll
        for (int i = 0; i < 8; i++) {
            int idx = tid + 256 * i;
            int r = idx >> 5, c4 = idx & 31;
            size_t gk = (size_t)(j0 + r) * QKVW + KOFF + kvh * HDIM + c4 * 4;
            size_t gv = (size_t)(j0 + r) * QKVW + VOFF + kvh * HDIM + c4 * 4;
            *(float4*)&Ks[r * 128 + c4 * 4] = *(const float4*)(g_qkv + gk);
            *(float4*)&Vs[r * 128 + c4 * 4] = *(const float4*)(g_qkv + gv);
        }
        __syncthreads();

        float tmax = -1e30f;
#pragma unroll 4
        for (int j = 0; j < 64; j++) {
            const float* kr = Ks + j * 128;
            float p = 0.f;
#pragma unroll
            for (int i = 0; i < 32; i++) p += qreg[i] * kr[4 * i + lane4];
            p += __shfl_xor_sync(0xffffffffu, p, 1);
            p += __shfl_xor_sync(0xffffffffu, p, 2);
            float s = p * scale + ((j0 + j <= tglob) ? 0.f : -1e9f);
            tmax = fmaxf(tmax, s);
            if ((j & 3) == lane4) Ss[row * 65 + j] = s;
        }
        __syncwarp();

        float m_new = fmaxf(m_i, tmax);
        float corr = __expf(m_i - m_new);
        l_i *= corr;
#pragma unroll
        for (int i = 0; i < 32; i++) acc[i] *= corr;

#pragma unroll 4
        for (int j = 0; j < 64; j++) {
            float pj = __expf(Ss[row * 65 + j] - m_new);
            l_i += pj;
            const float* vr = Vs + j * 128;
#pragma unroll
            for (int i = 0; i < 32; i++) acc[i] += pj * vr[4 * i + lane4];
        }
        m_i = m_new;
        __syncthreads();
    }

    float inv = 1.f / l_i;
    float* orow = g_attn + ((size_t)tglob * NQ + head) * HDIM;
#pragma unroll
    for (int i = 0; i < 32; i++) orow[4 * i + lane4] = acc[i] * inv;
}

// ================= routing =================
__global__ void zero_cnt_kernel() { if (threadIdx.x < NE) g_ecnt[threadIdx.x] = 0; }

__global__ void route_kernel(const float* __restrict__ gate_w)
{
    int t = blockIdx.x;
    int tid = threadIdx.x;
    const float* x = g_h2 + (size_t)t * DD;
    float acc[NE];
#pragma unroll
    for (int e = 0; e < NE; e++) acc[e] = 0.f;
    for (int d = tid; d < DD; d += 128) {
        float xv = x[d];
        const float* gw = gate_w + (size_t)d * NE;
#pragma unroll
        for (int e = 0; e < NE; e++) acc[e] += xv * gw[e];
    }
    __shared__ float s[NE * 128];
#pragma unroll
    for (int e = 0; e < NE; e++) s[e * 128 + tid] = acc[e];
    __syncthreads();
    __shared__ float logits[NE];
    if (tid < NE) {
        float sum = 0.f;
        for (int i = 0; i < 128; i++) sum += s[tid * 128 + i];
        logits[tid] = sum;
    }
    __syncthreads();
    if (tid == 0) {
        float mx = -1e30f;
        for (int e = 0; e < NE; e++) mx = fmaxf(mx, logits[e]);
        float p[NE], Z = 0.f;
        for (int e = 0; e < NE; e++) { p[e] = expf(logits[e] - mx); Z += p[e]; }
        for (int e = 0; e < NE; e++) p[e] /= Z;
        int idx[TOPK]; float val[TOPK]; bool used[NE] = {};
        float wsum = 0.f;
        for (int k = 0; k < TOPK; k++) {
            int best = -1; float bv = -1.f;
            for (int e = 0; e < NE; e++)
                if (!used[e] && p[e] > bv) { bv = p[e]; best = e; }
            used[best] = true; idx[k] = best; val[k] = bv; wsum += bv;
        }
        for (int k = 0; k < TOPK; k++) {
            int rowid = t * TOPK + k;
            g_rw[rowid] = val[k] / wsum;
            int e = idx[k];
            int pos = atomicAdd(&g_ecnt[e], 1);
            g_erows[e * TT + pos] = rowid;
        }
    }
}

__global__ void silu_kernel()
{
    size_t i = (size_t)blockIdx.x * 256 + threadIdx.x;
    int r = (int)(i >> 10);
    int f = (int)(i & 1023);
    float g = g_gu[(size_t)r * (2 * NF) + f];
    float u = g_gu[(size_t)r * (2 * NF) + NF + f];
    g_gated[i] = u * (g / (1.f + __expf(-g)));
}

__global__ void copy_out_kernel(float* __restrict__ out)
{
    size_t i = (size_t)blockIdx.x * 256 + threadIdx.x;
    ((float4*)out)[i] = ((const float4*)g_hmid)[i];
}

// ================= launch =================
extern "C" void kernel_launch(void* const* d_in, const int* in_sizes, int n_in,
                              void* d_out, int out_size)
{
    const float* hidden  = (const float*)d_in[0];
    const float* cosb    = (const float*)d_in[1];
    const float* sinb    = (const float*)d_in[2];
    const float* in_ln   = (const float*)d_in[4];
    const float* post_ln = (const float*)d_in[5];
    const float* q_w     = (const float*)d_in[6];
    const float* k_w     = (const float*)d_in[7];
    const float* v_w     = (const float*)d_in[8];
    const float* o_w     = (const float*)d_in[9];
    const float* q_nw    = (const float*)d_in[10];
    const float* k_nw    = (const float*)d_in[11];
    const float* gate_w  = (const float*)d_in[12];
    const float* gup_w   = (const float*)d_in[13];
    const float* down_w  = (const float*)d_in[14];
    float* out = (float*)d_out;

    float *hn, *qkv, *attn, *hmid, *h2, *gu;
    __nv_bfloat16 *qkvT_h, *qkvT_l, *owT_h, *owT_l, *guT_h, *guT_l, *dwT_h, *dwT_l;
    cudaGetSymbolAddress((void**)&hn,   g_hn);
    cudaGetSymbolAddress((void**)&qkv,  g_qkv);
    cudaGetSymbolAddress((void**)&attn, g_attn);
    cudaGetSymbolAddress((void**)&hmid, g_hmid);
    cudaGetSymbolAddress((void**)&h2,   g_h2);
    cudaGetSymbolAddress((void**)&gu,   g_gu);
    cudaGetSymbolAddress((void**)&qkvT_h, g_qkvT_h);
    cudaGetSymbolAddress((void**)&qkvT_l, g_qkvT_l);
    cudaGetSymbolAddress((void**)&owT_h,  g_owT_h);
    cudaGetSymbolAddress((void**)&owT_l,  g_owT_l);
    cudaGetSymbolAddress((void**)&guT_h,  g_guT_h);
    cudaGetSymbolAddress((void**)&guT_l,  g_guT_l);
    cudaGetSymbolAddress((void**)&dwT_h,  g_dwT_h);
    cudaGetSymbolAddress((void**)&dwT_l,  g_dwT_l);

    cudaFuncSetAttribute(hmma_gemm_kernel, cudaFuncAttributeMaxDynamicSharedMemorySize, HM_SMEM);
    const int ATTN_SMEM = ATTN_SMEM_FLOATS * (int)sizeof(float);
    cudaFuncSetAttribute(attn_kernel, cudaFuncAttributeMaxDynamicSharedMemorySize, ATTN_SMEM);

    dim3 tb(32, 8);
    // weight transpose + split-bf16 conversion
    tconv_kernel<<<dim3(64, 64, 1),  tb>>>(q_w,  qkvT_h,                     qkvT_l,                     DD, 2048);
    tconv_kernel<<<dim3(16, 64, 1),  tb>>>(k_w,  qkvT_h + (size_t)KOFF * DD, qkvT_l + (size_t)KOFF * DD, DD, 512);
    tconv_kernel<<<dim3(16, 64, 1),  tb>>>(v_w,  qkvT_h + (size_t)VOFF * DD, qkvT_l + (size_t)VOFF * DD, DD, 512);
    tconv_kernel<<<dim3(64, 64, 1),  tb>>>(o_w,  owT_h, owT_l, DD, 2048);
    tconv_kernel<<<dim3(64, 64, NE), tb>>>(gup_w, guT_h, guT_l, DD, 2048);
    tconv_kernel<<<dim3(64, 32, NE), tb>>>(down_w, dwT_h, dwT_l, NF, 2048);

    // 1. pre-attn rmsnorm
    rmsnorm_kernel<<<TT, 256>>>(hidden, in_ln, hn);
    // 2. fused QKV projection (N=3072)
    hmma_gemm_kernel<<<dim3(QKVW / 128, TT / 128), 256, HM_SMEM>>>(
        0, hn, qkvT_h, qkvT_l, qkv, nullptr, QKVW, DD);
    // 3. per-head norm + rope
    normrope_kernel<<<dim3(TT, NQ + NKV), 128>>>(cosb, sinb, q_nw, k_nw);
    // 4. attention
    attn_kernel<<<dim3(TT / 64, NQ), 256, ATTN_SMEM>>>();
    // 5. O projection + residual
    hmma_gemm_kernel<<<dim3(DD / 128, TT / 128), 256, HM_SMEM>>>(
        0, attn, owT_h, owT_l, hmid, hidden, DD, DD);
    // 6. post-attn rmsnorm
    rmsnorm_kernel<<<TT, 256>>>(hmid, post_ln, h2);
    // 7. routing
    zero_cnt_kernel<<<1, 32>>>();
    route_kernel<<<TT, 128>>>(gate_w);
    // 8. init output with residual, then sparse expert GEMMs
    copy_out_kernel<<<TT * DD / 4 / 256, 256>>>(out);
    hmma_gemm_kernel<<<dim3((2 * NF) / 128, 16, NE), 256, HM_SMEM>>>(
        1, nullptr, guT_h, guT_l, gu, nullptr, 2 * NF, DD);
    silu_kernel<<<(TT * TOPK * NF) / 256, 256>>>();
    hmma_gemm_kernel<<<dim3(DD / 128, 16, NE), 256, HM_SMEM>>>(
        2, nullptr, dwT_h, dwT_l, out, nullptr, DD, NF);
}

// round 7
// speedup vs baseline: 1.6865x; 1.1025x over previous
#include <cuda_runtime.h>
#include <cuda_bf16.h>
#include <math.h>
#include <stdint.h>

#define TT   2048
#define DD   2048
#define NQ   16
#define NKV  4
#define HDIM 128
#define NE   16
#define NF   1024
#define TOPK 4

#define QKVW 3072          // fused qkv width: q 0..2047, k 2048..2559, v 2560..3071
#define KOFF 2048
#define VOFF 2560

// ---------------- scratch (static device globals; no allocation) ----------------
__device__ float g_qkv  [TT * QKVW];          // fp32 (attention wants precision)
__device__ float g_hmid [TT * DD];            // residual + attn out (fp32)
__device__ float g_h2   [TT * DD];            // rmsnorm2 fp32 (for router)
__device__ float g_gu   [TT * TOPK * 2 * NF];
__device__ float g_rw   [TT * TOPK];
__device__ int   g_ecnt [NE];
__device__ int   g_erows[NE * TT];

// split-bf16 activations (produced by rmsnorm/attn/silu epilogues)
__device__ __nv_bfloat16 g_hn_h   [TT * DD];
__device__ __nv_bfloat16 g_hn_l   [TT * DD];
__device__ __nv_bfloat16 g_attn_h [TT * DD];
__device__ __nv_bfloat16 g_attn_l [TT * DD];
__device__ __nv_bfloat16 g_h2_h   [TT * DD];
__device__ __nv_bfloat16 g_h2_l   [TT * DD];
__device__ __nv_bfloat16 g_gated_h[TT * TOPK * NF];
__device__ __nv_bfloat16 g_gated_l[TT * TOPK * NF];

// transposed + split-bf16 weights  (layout: [N rows][K], K contiguous)
__device__ __nv_bfloat16 g_qkvT_h[QKVW * DD];
__device__ __nv_bfloat16 g_qkvT_l[QKVW * DD];
__device__ __nv_bfloat16 g_owT_h [DD * DD];
__device__ __nv_bfloat16 g_owT_l [DD * DD];
__device__ __nv_bfloat16 g_guT_h [NE * (2 * NF) * DD];
__device__ __nv_bfloat16 g_guT_l [NE * (2 * NF) * DD];
__device__ __nv_bfloat16 g_dwT_h [NE * DD * NF];
__device__ __nv_bfloat16 g_dwT_l [NE * DD * NF];

// ================= helpers =================
__device__ __forceinline__ uint32_t smem_u32(const void* p) {
    uint32_t r;
    asm("{ .reg .u64 t; cvta.to.shared.u64 t, %1; cvt.u32.u64 %0, t; }" : "=r"(r) : "l"(p));
    return r;
}
__device__ __forceinline__ uint32_t pack2bf(__nv_bfloat16 a, __nv_bfloat16 b) {
    return (uint32_t)__bfloat16_as_ushort(a) | ((uint32_t)__bfloat16_as_ushort(b) << 16);
}
__device__ __forceinline__ void ldsm4(uint32_t* r, uint32_t a) {
    asm volatile("ldmatrix.sync.aligned.m8n8.x4.shared.b16 {%0,%1,%2,%3}, [%4];"
                 : "=r"(r[0]), "=r"(r[1]), "=r"(r[2]), "=r"(r[3]) : "r"(a));
}
__device__ __forceinline__ void mma16816(float* c, const uint32_t* a, const uint32_t* b) {
    asm volatile("mma.sync.aligned.m16n8k16.row.col.f32.bf16.bf16.f32 "
                 "{%0,%1,%2,%3}, {%4,%5,%6,%7}, {%8,%9}, {%0,%1,%2,%3};"
                 : "+f"(c[0]), "+f"(c[1]), "+f"(c[2]), "+f"(c[3])
                 : "r"(a[0]), "r"(a[1]), "r"(a[2]), "r"(a[3]), "r"(b[0]), "r"(b[1]));
}
#define CP16(dst, src) \
    asm volatile("cp.async.cg.shared.global [%0], [%1], 16;" :: "r"(dst), "l"(src))
#define CP_COMMIT() asm volatile("cp.async.commit_group;" ::: "memory")
#define CP_WAIT1()  asm volatile("cp.async.wait_group 1;" ::: "memory")
#define CP_WAIT0()  asm volatile("cp.async.wait_group 0;" ::: "memory")

__device__ __forceinline__ void split_bf16(float v, __nv_bfloat16& h, __nv_bfloat16& l) {
    h = __float2bfloat16(v);
    l = __float2bfloat16(v - __bfloat162float(h));
}

// ================= transpose + split-convert: in[K,N] -> hi/lo [N,K] =================
__global__ void tconv_kernel(const float* __restrict__ in,
                             __nv_bfloat16* __restrict__ oh,
                             __nv_bfloat16* __restrict__ ol,
                             int K, int N)
{
    __shared__ float t[32][33];
    int n0 = blockIdx.x * 32, k0 = blockIdx.y * 32;
    size_t ib = (size_t)blockIdx.z * K * N;
    int tx = threadIdx.x, ty = threadIdx.y;
#pragma unroll
    for (int j = 0; j < 32; j += 8)
        t[ty + j][tx] = in[ib + (size_t)(k0 + ty + j) * N + n0 + tx];
    __syncthreads();
#pragma unroll
    for (int j = 0; j < 32; j += 8) {
        float v = t[tx][ty + j];
        __nv_bfloat16 h, l;
        split_bf16(v, h, l);
        size_t o = ib + (size_t)(n0 + ty + j) * K + k0 + tx;
        oh[o] = h;
        ol[o] = l;
    }
}

// ================= bf16x3 GEMM, cp.async 3-stage pipeline =================
// CTA 128(M) x 256(N), KC=32, 16 warps (4m x 4n), warp tile 32x64.
// Both A and B are pre-split bf16 hi/lo in gmem; [row][K] with K contiguous.
// mode 0: dense  C[M,N] = A @ B^T (+addsrc)
// mode 1: moe gate_up: A rows = g_h2*[erows>>2], C rows = g_gu[erows]
// mode 2: moe down: A rows = g_gated*[erows], atomicAdd into C[tok] * g_rw
#define KC 32
#define RST 80                 // smem row stride (bytes) for 32 bf16 + pad
#define A_SZ  (128 * RST)      // 10240 per hi or lo
#define B_SZ  (256 * RST)      // 20480
#define STG   (2 * A_SZ + 2 * B_SZ)   // 61440 per stage
#define ALO_R A_SZ             // offsets within a stage
#define BHI_R (2 * A_SZ)
#define BLO_R (2 * A_SZ + B_SZ)
#define EROFF (3 * STG)
#define GEMM_SMEM (EROFF + 512)

__global__ void __launch_bounds__(512) bf16x3_gemm_kernel(
    int mode,
    const __nv_bfloat16* __restrict__ Ah, const __nv_bfloat16* __restrict__ Al,
    const __nv_bfloat16* __restrict__ Bh, const __nv_bfloat16* __restrict__ Bl,
    float* __restrict__ C, const float* __restrict__ addsrc, int N, int K)
{
    int e  = blockIdx.z;
    int m0 = blockIdx.y * 128;
    int n0 = blockIdx.x * 256;
    int cnt = 0;
    if (mode != 0) {
        cnt = g_ecnt[e];
        if (m0 >= cnt) return;
        Bh += (size_t)e * N * K;
        Bl += (size_t)e * N * K;
    }
    extern __shared__ char sm[];
    uint32_t sb = smem_u32(sm);
    int tid = threadIdx.x, wid = tid >> 5, l = tid & 31;
    int* erows_s = (int*)(sm + EROFF);
    if (mode != 0 && tid < 128)
        erows_s[tid] = (m0 + tid < cnt) ? g_erows[e * TT + m0 + tid] : 0;
    __syncthreads();

    // ---- cp.async per-thread mappings ----
    int arow = tid >> 2, apart = tid & 3;     // A: 128 rows, 4x16B per row
    size_t aro;
    if (mode == 0)      aro = (size_t)(m0 + arow) * K;
    else if (mode == 1) aro = (size_t)(erows_s[arow] >> 2) * DD;
    else                aro = (size_t)erows_s[arow] * NF;
    const __nv_bfloat16* aph = Ah + aro + apart * 8;
    const __nv_bfloat16* apl = Al + aro + apart * 8;
    uint32_t a_dst = (uint32_t)(arow * RST + apart * 16);

    size_t bo0 = (size_t)(n0 + arow) * K + apart * 8;        // B rows in 2 halves
    size_t bo1 = (size_t)(n0 + arow + 128) * K + apart * 8;
    uint32_t b_dst0 = (uint32_t)(arow * RST + apart * 16);
    uint32_t b_dst1 = (uint32_t)((arow + 128) * RST + apart * 16);

    int NC = K / KC;

    // ---- fragment smem offsets (R5-proven mapping, 80B stride) ----
    int wm = wid >> 2, wn = wid & 3;
    int a_r = (l & 7) + ((l >> 3) & 1) * 8, a_c = (l >> 4) * 8;
    int b_r = (l & 7) + (l >> 4) * 8,       b_c = ((l >> 3) & 1) * 8;
    uint32_t aoff = (uint32_t)((wm * 32 + a_r) * RST + a_c * 2);
    uint32_t boff = (uint32_t)(BHI_R + (wn * 64 + b_r) * RST + b_c * 2);

    float acc[2][8][4];
#pragma unroll
    for (int mi = 0; mi < 2; mi++)
#pragma unroll
        for (int ni = 0; ni < 8; ni++)
#pragma unroll
            for (int j = 0; j < 4; j++) acc[mi][ni][j] = 0.f;

    // ---- prologue: stages 0,1 ----
#pragma unroll
    for (int p = 0; p < 2; p++) {
        if (p < NC) {
            uint32_t st = sb + p * STG;
            int k0 = p * KC;
            CP16(st + a_dst, aph + k0);
            CP16(st + ALO_R + a_dst, apl + k0);
            CP16(st + BHI_R + b_dst0, Bh + bo0 + k0);
            CP16(st + BHI_R + b_dst1, Bh + bo1 + k0);
            CP16(st + BLO_R + b_dst0, Bl + bo0 + k0);
            CP16(st + BLO_R + b_dst1, Bl + bo1 + k0);
        }
        CP_COMMIT();
    }

    for (int c = 0; c < NC; c++) {
        if (c + 1 < NC) CP_WAIT1(); else CP_WAIT0();
        __syncthreads();
        if (c + 2 < NC) {
            int nc2 = c + 2;
            uint32_t st = sb + (nc2 % 3) * STG;
            int k0 = nc2 * KC;
            CP16(st + a_dst, aph + k0);
            CP16(st + ALO_R + a_dst, apl + k0);
            CP16(st + BHI_R + b_dst0, Bh + bo0 + k0);
            CP16(st + BHI_R + b_dst1, Bh + bo1 + k0);
            CP16(st + BLO_R + b_dst0, Bl + bo0 + k0);
            CP16(st + BLO_R + b_dst1, Bl + bo1 + k0);
        }
        CP_COMMIT();

        uint32_t st = sb + (c % 3) * STG;
#pragma unroll
        for (int kk = 0; kk < 2; kk++) {
            uint32_t bh[4][4], bl4[4][4];
#pragma unroll
            for (int q = 0; q < 4; q++) {
                ldsm4(bh[q],  st + boff + q * (16 * RST) + kk * 32);
                ldsm4(bl4[q], st + boff + B_SZ + q * (16 * RST) + kk * 32);
            }
#pragma unroll
            for (int mi = 0; mi < 2; mi++) {
                uint32_t ah4[4], al4[4];
                ldsm4(ah4, st + aoff + mi * (16 * RST) + kk * 32);
                ldsm4(al4, st + aoff + ALO_R + mi * (16 * RST) + kk * 32);
#pragma unroll
                for (int q = 0; q < 4; q++) {
                    mma16816(acc[mi][q * 2],     ah4, &bh[q][0]);
                    mma16816(acc[mi][q * 2],     ah4, &bl4[q][0]);
                    mma16816(acc[mi][q * 2],     al4, &bh[q][0]);
                    mma16816(acc[mi][q * 2 + 1], ah4, &bh[q][2]);
                    mma16816(acc[mi][q * 2 + 1], ah4, &bl4[q][2]);
                    mma16816(acc[mi][q * 2 + 1], al4, &bh[q][2]);
                }
            }
        }
    }

    // ---- epilogue ----
    int g = l >> 2, tig = l & 3;
#pragma unroll
    for (int mi = 0; mi < 2; mi++) {
        int r0 = wm * 32 + mi * 16 + g;
        int r1 = r0 + 8;
        bool v0 = true, v1 = true;
        size_t ro0 = 0, ro1 = 0;
        float w0 = 0.f, w1 = 0.f;
        if (mode == 0) {
            ro0 = (size_t)(m0 + r0) * N;
            ro1 = (size_t)(m0 + r1) * N;
        } else {
            v0 = (m0 + r0) < cnt;
            v1 = (m0 + r1) < cnt;
            int rowid0 = erows_s[r0], rowid1 = erows_s[r1];
            if (mode == 1) {
                ro0 = (size_t)rowid0 * (2 * NF);
                ro1 = (size_t)rowid1 * (2 * NF);
            } else {
                ro0 = (size_t)(rowid0 >> 2) * DD;
                ro1 = (size_t)(rowid1 >> 2) * DD;
                if (v0) w0 = g_rw[rowid0];
                if (v1) w1 = g_rw[rowid1];
            }
        }
#pragma unroll
        for (int ni = 0; ni < 8; ni++) {
            int cc = n0 + wn * 64 + ni * 8 + tig * 2;
            float* a = acc[mi][ni];
            if (mode == 0) {
                if (addsrc) {
                    float2 s0 = *(const float2*)(addsrc + ro0 + cc);
                    float2 s1 = *(const float2*)(addsrc + ro1 + cc);
                    *(float2*)(C + ro0 + cc) = make_float2(a[0] + s0.x, a[1] + s0.y);
                    *(float2*)(C + ro1 + cc) = make_float2(a[2] + s1.x, a[3] + s1.y);
                } else {
                    *(float2*)(C + ro0 + cc) = make_float2(a[0], a[1]);
                    *(float2*)(C + ro1 + cc) = make_float2(a[2], a[3]);
                }
            } else if (mode == 1) {
                if (v0) *(float2*)(C + ro0 + cc) = make_float2(a[0], a[1]);
                if (v1) *(float2*)(C + ro1 + cc) = make_float2(a[2], a[3]);
            } else {
                if (v0) { atomicAdd(C + ro0 + cc, w0 * a[0]); atomicAdd(C + ro0 + cc + 1, w0 * a[1]); }
                if (v1) { atomicAdd(C + ro1 + cc, w1 * a[2]); atomicAdd(C + ro1 + cc + 1, w1 * a[3]); }
            }
        }
    }
}

// ================= RMSNorm over D=2048, split-bf16 (+optional fp32) out =================
__global__ void rmsnorm_kernel(const float* __restrict__ x,
                               const float* __restrict__ w,
                               float* __restrict__ ofp,
                               __nv_bfloat16* __restrict__ oh,
                               __nv_bfloat16* __restrict__ ol)
{
    int t = blockIdx.x;
    const float4* xr = (const float4*)(x + (size_t)t * DD);
    const float4* wr = (const float4*)w;
    int tid = threadIdx.x;
    float4 v0 = xr[tid], v1 = xr[tid + 256];
    float ss = v0.x*v0.x + v0.y*v0.y + v0.z*v0.z + v0.w*v0.w
             + v1.x*v1.x + v1.y*v1.y + v1.z*v1.z + v1.w*v1.w;
#pragma unroll
    for (int o = 16; o; o >>= 1) ss += __shfl_xor_sync(0xffffffffu, ss, o);
    __shared__ float red[8];
    if ((tid & 31) == 0) red[tid >> 5] = ss;
    __syncthreads();
    float tot = red[0]+red[1]+red[2]+red[3]+red[4]+red[5]+red[6]+red[7];
    float r = rsqrtf(tot / (float)DD + 1e-6f);
    float4 w0 = wr[tid], w1 = wr[tid + 256];
    float4 o0, o1;
    o0.x = v0.x*r*w0.x; o0.y = v0.y*r*w0.y; o0.z = v0.z*r*w0.z; o0.w = v0.w*r*w0.w;
    o1.x = v1.x*r*w1.x; o1.y = v1.y*r*w1.y; o1.z = v1.z*r*w1.z; o1.w = v1.w*r*w1.w;
    if (ofp) {
        float4* orow = (float4*)(ofp + (size_t)t * DD);
        orow[tid] = o0; orow[tid + 256] = o1;
    }
    __nv_bfloat16 h[8], lo[8];
    split_bf16(o0.x, h[0], lo[0]); split_bf16(o0.y, h[1], lo[1]);
    split_bf16(o0.z, h[2], lo[2]); split_bf16(o0.w, h[3], lo[3]);
    split_bf16(o1.x, h[4], lo[4]); split_bf16(o1.y, h[5], lo[5]);
    split_bf16(o1.z, h[6], lo[6]); split_bf16(o1.w, h[7], lo[7]);
    uint2* ohr = (uint2*)(oh + (size_t)t * DD);
    uint2* olr = (uint2*)(ol + (size_t)t * DD);
    ohr[tid]       = make_uint2(pack2bf(h[0], h[1]),  pack2bf(h[2], h[3]));
    ohr[tid + 256] = make_uint2(pack2bf(h[4], h[5]),  pack2bf(h[6], h[7]));
    olr[tid]       = make_uint2(pack2bf(lo[0], lo[1]), pack2bf(lo[2], lo[3]));
    olr[tid + 256] = make_uint2(pack2bf(lo[4], lo[5]), pack2bf(lo[6], lo[7]));
}

// ================= per-head RMSNorm + RoPE (in place on g_qkv, fp32) =================
__global__ void normrope_kernel(const float* __restrict__ cosb,
                                const float* __restrict__ sinb,
                                const float* __restrict__ qnw,
                                const float* __restrict__ knw)
{
    int t = blockIdx.x;
    int head = blockIdx.y;      // 0..15 q, 16..19 k
    int h = threadIdx.x;
    float* buf;
    const float* nw;
    if (head < NQ) { buf = g_qkv + (size_t)t * QKVW + head * HDIM;               nw = qnw; }
    else           { buf = g_qkv + (size_t)t * QKVW + KOFF + (head - NQ) * HDIM; nw = knw; }
    float v = buf[h];
    float ss = v * v;
#pragma unroll
    for (int o = 16; o; o >>= 1) ss += __shfl_xor_sync(0xffffffffu, ss, o);
    __shared__ float red[4];
    __shared__ float xs[128];
    if ((h & 31) == 0) red[h >> 5] = ss;
    __syncthreads();
    float tot = red[0] + red[1] + red[2] + red[3];
    float xn = v * rsqrtf(tot / (float)HDIM + 1e-6f) * nw[h];
    xs[h] = xn;
    __syncthreads();
    float c = cosb[(size_t)t * HDIM + h];
    float s = sinb[(size_t)t * HDIM + h];
    float other = (h < 64) ? xs[h + 64] : xs[h - 64];
    buf[h] = (h < 64) ? (xn * c - other * s) : (xn * c + other * s);
}

// ================= flash attention (fp32; split-bf16 output) =================
#define ATTN_SMEM_FLOATS (64*128 + 64*128 + 64*65)
__global__ void __launch_bounds__(256) attn_kernel()
{
    extern __shared__ float smf[];
    float* Ks = smf;
    float* Vs = smf + 64 * 128;
    float* Ss = smf + 2 * 64 * 128;
    int m0 = blockIdx.x * 64;
    int head = blockIdx.y;
    int kvh = head >> 2;
    int tid = threadIdx.x;
    int row = tid >> 2;
    int lane4 = tid & 3;
    int tglob = m0 + row;
    const float scale = 0.08838834764831843f;

    float qreg[32];
    const float* qrow = g_qkv + (size_t)tglob * QKVW + head * HDIM;
#pragma unroll
    for (int i = 0; i < 32; i++) qreg[i] = qrow[4 * i + lane4];

    float acc[32];
#pragma unroll
    for (int i = 0; i < 32; i++) acc[i] = 0.f;
    float m_i = -1e30f, l_i = 0.f;

    int jend = m0 + 64;
    for (int j0 = 0; j0 < jend; j0 += 64) {
#pragma unroll
        for (int i = 0; i < 8; i++) {
            int idx = tid + 256 * i;
            int r = idx >> 5, c4 = idx & 31;
            size_t gk = (size_t)(j0 + r) * QKVW + KOFF + kvh * HDIM + c4 * 4;
            size_t gv = (size_t)(j0 + r) * QKVW + VOFF + kvh * HDIM + c4 * 4;
            *(float4*)&Ks[r * 128 + c4 * 4] = *(const float4*)(g_qkv + gk);
            *(float4*)&Vs[r * 128 + c4 * 4] = *(const float4*)(g_qkv + gv);
        }
        __syncthreads();

        float tmax = -1e30f;
#pragma unroll 4
        for (int j = 0; j < 64; j++) {
            const float* kr = Ks + j * 128;
            float p = 0.f;
#pragma unroll
            for (int i = 0; i < 32; i++) p += qreg[i] * kr[4 * i + lane4];
            p += __shfl_xor_sync(0xffffffffu, p, 1);
            p += __shfl_xor_sync(0xffffffffu, p, 2);
            float s = p * scale + ((j0 + j <= tglob) ? 0.f : -1e9f);
            tmax = fmaxf(tmax, s);
            if ((j & 3) == lane4) Ss[row * 65 + j] = s;
        }
        __syncwarp();

        float m_new = fmaxf(m_i, tmax);
        float corr = __expf(m_i - m_new);
        l_i *= corr;
#pragma unroll
        for (int i = 0; i < 32; i++) acc[i] *= corr;

#pragma unroll 4
        for (int j = 0; j < 64; j++) {
            float pj = __expf(Ss[row * 65 + j] - m_new);
            l_i += pj;
            const float* vr = Vs + j * 128;
#pragma unroll
            for (int i = 0; i < 32; i++) acc[i] += pj * vr[4 * i + lane4];
        }
        m_i = m_new;
        __syncthreads();
    }

    float inv = 1.f / l_i;
    // output row-major [T][NQ*HDIM] = [T][2048] split-bf16
    size_t obase = (size_t)tglob * DD + head * HDIM;
#pragma unroll
    for (int i = 0; i < 32; i++) {
        float v = acc[i] * inv;
        __nv_bfloat16 h, lo;
        split_bf16(v, h, lo);
        g_attn_h[obase + 4 * i + lane4] = h;
        g_attn_l[obase + 4 * i + lane4] = lo;
    }
}

// ================= routing =================
__global__ void zero_cnt_kernel() { if (threadIdx.x < NE) g_ecnt[threadIdx.x] = 0; }

__global__ void route_kernel(const float* __restrict__ gate_w)
{
    int t = blockIdx.x;
    int tid = threadIdx.x;
    const float* x = g_h2 + (size_t)t * DD;
    float acc[NE];
#pragma unroll
    for (int e = 0; e < NE; e++) acc[e] = 0.f;
    for (int d = tid; d < DD; d += 128) {
        float xv = x[d];
        const float* gw = gate_w + (size_t)d * NE;
#pragma unroll
        for (int e = 0; e < NE; e++) acc[e] += xv * gw[e];
    }
    __shared__ float s[NE * 128];
#pragma unroll
    for (int e = 0; e < NE; e++) s[e * 128 + tid] = acc[e];
    __syncthreads();
    __shared__ float logits[NE];
    if (tid < NE) {
        float sum = 0.f;
        for (int i = 0; i < 128; i++) sum += s[tid * 128 + i];
        logits[tid] = sum;
    }
    __syncthreads();
    if (tid == 0) {
        float mx = -1e30f;
        for (int e = 0; e < NE; e++) mx = fmaxf(mx, logits[e]);
        float p[NE], Z = 0.f;
        for (int e = 0; e < NE; e++) { p[e] = expf(logits[e] - mx); Z += p[e]; }
        for (int e = 0; e < NE; e++) p[e] /= Z;
        int idx[TOPK]; float val[TOPK]; bool used[NE] = {};
        float wsum = 0.f;
        for (int k = 0; k < TOPK; k++) {
            int best = -1; float bv = -1.f;
            for (int e = 0; e < NE; e++)
                if (!used[e] && p[e] > bv) { bv = p[e]; best = e; }
            used[best] = true; idx[k] = best; val[k] = bv; wsum += bv;
        }
        for (int k = 0; k < TOPK; k++) {
            int rowid = t * TOPK + k;
            g_rw[rowid] = val[k] / wsum;
            int e = idx[k];
            int pos = atomicAdd(&g_ecnt[e], 1);
            g_erows[e * TT + pos] = rowid;
        }
    }
}

__global__ void silu_kernel()
{
    size_t i = (size_t)blockIdx.x * 256 + threadIdx.x;
    int r = (int)(i >> 10);
    int f = (int)(i & 1023);
    float g = g_gu[(size_t)r * (2 * NF) + f];
    float u = g_gu[(size_t)r * (2 * NF) + NF + f];
    float v = u * (g / (1.f + __expf(-g)));
    __nv_bfloat16 h, lo;
    split_bf16(v, h, lo);
    g_gated_h[i] = h;
    g_gated_l[i] = lo;
}

__global__ void copy_out_kernel(float* __restrict__ out)
{
    size_t i = (size_t)blockIdx.x * 256 + threadIdx.x;
    ((float4*)out)[i] = ((const float4*)g_hmid)[i];
}

// ================= launch =================
extern "C" void kernel_launch(void* const* d_in, const int* in_sizes, int n_in,
                              void* d_out, int out_size)
{
    const float* hidden  = (const float*)d_in[0];
    const float* cosb    = (const float*)d_in[1];
    const float* sinb    = (const float*)d_in[2];
    const float* in_ln   = (const float*)d_in[4];
    const float* post_ln = (const float*)d_in[5];
    const float* q_w     = (const float*)d_in[6];
    const float* k_w     = (const float*)d_in[7];
    const float* v_w     = (const float*)d_in[8];
    const float* o_w     = (const float*)d_in[9];
    const float* q_nw    = (const float*)d_in[10];
    const float* k_nw    = (const float*)d_in[11];
    const float* gate_w  = (const float*)d_in[12];
    const float* gup_w   = (const float*)d_in[13];
    const float* down_w  = (const float*)d_in[14];
    float* out = (float*)d_out;

    float *qkv, *hmid, *h2, *gu;
    __nv_bfloat16 *hn_h, *hn_l, *attn_h, *attn_l, *h2_h, *h2_l, *gated_h, *gated_l;
    __nv_bfloat16 *qkvT_h, *qkvT_l, *owT_h, *owT_l, *guT_h, *guT_l, *dwT_h, *dwT_l;
    cudaGetSymbolAddress((void**)&qkv,  g_qkv);
    cudaGetSymbolAddress((void**)&hmid, g_hmid);
    cudaGetSymbolAddress((void**)&h2,   g_h2);
    cudaGetSymbolAddress((void**)&gu,   g_gu);
    cudaGetSymbolAddress((void**)&hn_h, g_hn_h);
    cudaGetSymbolAddress((void**)&hn_l, g_hn_l);
    cudaGetSymbolAddress((void**)&attn_h, g_attn_h);
    cudaGetSymbolAddress((void**)&attn_l, g_attn_l);
    cudaGetSymbolAddress((void**)&h2_h, g_h2_h);
    cudaGetSymbolAddress((void**)&h2_l, g_h2_l);
    cudaGetSymbolAddress((void**)&gated_h, g_gated_h);
    cudaGetSymbolAddress((void**)&gated_l, g_gated_l);
    cudaGetSymbolAddress((void**)&qkvT_h, g_qkvT_h);
    cudaGetSymbolAddress((void**)&qkvT_l, g_qkvT_l);
    cudaGetSymbolAddress((void**)&owT_h,  g_owT_h);
    cudaGetSymbolAddress((void**)&owT_l,  g_owT_l);
    cudaGetSymbolAddress((void**)&guT_h,  g_guT_h);
    cudaGetSymbolAddress((void**)&guT_l,  g_guT_l);
    cudaGetSymbolAddress((void**)&dwT_h,  g_dwT_h);
    cudaGetSymbolAddress((void**)&dwT_l,  g_dwT_l);

    cudaFuncSetAttribute(bf16x3_gemm_kernel, cudaFuncAttributeMaxDynamicSharedMemorySize, GEMM_SMEM);
    const int ATTN_SMEM = ATTN_SMEM_FLOATS * (int)sizeof(float);
    cudaFuncSetAttribute(attn_kernel, cudaFuncAttributeMaxDynamicSharedMemorySize, ATTN_SMEM);

    dim3 tb(32, 8);
    // weight transpose + split-bf16 conversion
    tconv_kernel<<<dim3(64, 64, 1),  tb>>>(q_w,  qkvT_h,                     qkvT_l,                     DD, 2048);
    tconv_kernel<<<dim3(16, 64, 1),  tb>>>(k_w,  qkvT_h + (size_t)KOFF * DD, qkvT_l + (size_t)KOFF * DD, DD, 512);
    tconv_kernel<<<dim3(16, 64, 1),  tb>>>(v_w,  qkvT_h + (size_t)VOFF * DD, qkvT_l + (size_t)VOFF * DD, DD, 512);
    tconv_kernel<<<dim3(64, 64, 1),  tb>>>(o_w,  owT_h, owT_l, DD, 2048);
    tconv_kernel<<<dim3(64, 64, NE), tb>>>(gup_w, guT_h, guT_l, DD, 2048);
    tconv_kernel<<<dim3(64, 32, NE), tb>>>(down_w, dwT_h, dwT_l, NF, 2048);

    // 1. pre-attn rmsnorm (split-bf16 out)
    rmsnorm_kernel<<<TT, 256>>>(hidden, in_ln, nullptr, hn_h, hn_l);
    // 2. fused QKV projection (N=3072)
    bf16x3_gemm_kernel<<<dim3(QKVW / 256, TT / 128), 512, GEMM_SMEM>>>(
        0, hn_h, hn_l, qkvT_h, qkvT_l, qkv, nullptr, QKVW, DD);
    // 3. per-head norm + rope (fp32)
    normrope_kernel<<<dim3(TT, NQ + NKV), 128>>>(cosb, sinb, q_nw, k_nw);
    // 4. attention (fp32; split-bf16 out)
    attn_kernel<<<dim3(TT / 64, NQ), 256, ATTN_SMEM>>>();
    // 5. O projection + residual
    bf16x3_gemm_kernel<<<dim3(DD / 256, TT / 128), 512, GEMM_SMEM>>>(
        0, attn_h, attn_l, owT_h, owT_l, hmid, hidden, DD, DD);
    // 6. post-attn rmsnorm (fp32 for router + split-bf16 for gemm)
    rmsnorm_kernel<<<TT, 256>>>(hmid, post_ln, h2, h2_h, h2_l);
    // 7. routing
    zero_cnt_kernel<<<1, 32>>>();
    route_kernel<<<TT, 128>>>(gate_w);
    // 8. init output with residual, then sparse expert GEMMs
    copy_out_kernel<<<TT * DD / 4 / 256, 256>>>(out);
    bf16x3_gemm_kernel<<<dim3((2 * NF) / 256, 16, NE), 512, GEMM_SMEM>>>(
        1, h2_h, h2_l, guT_h, guT_l, gu, nullptr, 2 * NF, DD);
    silu_kernel<<<(TT * TOPK * NF) / 256, 256>>>();
    bf16x3_gemm_kernel<<<dim3(DD / 256, 16, NE), 512, GEMM_SMEM>>>(
        2, gated_h, gated_l, dwT_h, dwT_l, out, nullptr, DD, NF);
}

// round 8
// speedup vs baseline: 2.6612x; 1.5779x over previous
#include <cuda_runtime.h>
#include <cuda_bf16.h>
#include <math.h>
#include <stdint.h>

#define TT   2048
#define DD   2048
#define NQ   16
#define NKV  4
#define HDIM 128
#define NE   16
#define NF   1024
#define TOPK 4

#define QKVW 3072          // fused qkv width: q 0..2047, k 2048..2559, v 2560..3071
#define KOFF 2048
#define VOFF 2560

// ---------------- scratch (static device globals; no allocation) ----------------
__device__ float g_qkv  [TT * QKVW];          // fp32 QKV gemm output
__device__ float g_hmid [TT * DD];            // residual + attn out (fp32)
__device__ float g_h2   [TT * DD];            // rmsnorm2 fp32 (for router)
__device__ float g_gu   [TT * TOPK * 2 * NF];
__device__ float g_rw   [TT * TOPK];
__device__ int   g_ecnt [NE];
__device__ int   g_erows[NE * TT];

// split-bf16 activations
__device__ __nv_bfloat16 g_hn_h   [TT * DD];
__device__ __nv_bfloat16 g_hn_l   [TT * DD];
__device__ __nv_bfloat16 g_q_h    [TT * NQ * HDIM];
__device__ __nv_bfloat16 g_q_l    [TT * NQ * HDIM];
__device__ __nv_bfloat16 g_k_h    [TT * NKV * HDIM];
__device__ __nv_bfloat16 g_k_l    [TT * NKV * HDIM];
__device__ __nv_bfloat16 g_v_h    [TT * NKV * HDIM];
__device__ __nv_bfloat16 g_v_l    [TT * NKV * HDIM];
__device__ __nv_bfloat16 g_attn_h [TT * DD];
__device__ __nv_bfloat16 g_attn_l [TT * DD];
__device__ __nv_bfloat16 g_h2_h   [TT * DD];
__device__ __nv_bfloat16 g_h2_l   [TT * DD];
__device__ __nv_bfloat16 g_gated_h[TT * TOPK * NF];
__device__ __nv_bfloat16 g_gated_l[TT * TOPK * NF];

// transposed + split-bf16 weights  (layout: [N rows][K], K contiguous)
__device__ __nv_bfloat16 g_qkvT_h[QKVW * DD];
__device__ __nv_bfloat16 g_qkvT_l[QKVW * DD];
__device__ __nv_bfloat16 g_owT_h [DD * DD];
__device__ __nv_bfloat16 g_owT_l [DD * DD];
__device__ __nv_bfloat16 g_guT_h [NE * (2 * NF) * DD];
__device__ __nv_bfloat16 g_guT_l [NE * (2 * NF) * DD];
__device__ __nv_bfloat16 g_dwT_h [NE * DD * NF];
__device__ __nv_bfloat16 g_dwT_l [NE * DD * NF];

// ================= helpers =================
__device__ __forceinline__ uint32_t smem_u32(const void* p) {
    uint32_t r;
    asm("{ .reg .u64 t; cvta.to.shared.u64 t, %1; cvt.u32.u64 %0, t; }" : "=r"(r) : "l"(p));
    return r;
}
__device__ __forceinline__ uint32_t pack2bf(__nv_bfloat16 a, __nv_bfloat16 b) {
    return (uint32_t)__bfloat16_as_ushort(a) | ((uint32_t)__bfloat16_as_ushort(b) << 16);
}
__device__ __forceinline__ void ldsm4(uint32_t* r, uint32_t a) {
    asm volatile("ldmatrix.sync.aligned.m8n8.x4.shared.b16 {%0,%1,%2,%3}, [%4];"
                 : "=r"(r[0]), "=r"(r[1]), "=r"(r[2]), "=r"(r[3]) : "r"(a));
}
__device__ __forceinline__ void ldsm4t(uint32_t* r, uint32_t a) {
    asm volatile("ldmatrix.sync.aligned.m8n8.x4.trans.shared.b16 {%0,%1,%2,%3}, [%4];"
                 : "=r"(r[0]), "=r"(r[1]), "=r"(r[2]), "=r"(r[3]) : "r"(a));
}
__device__ __forceinline__ void mma16816(float* c, const uint32_t* a, const uint32_t* b) {
    asm volatile("mma.sync.aligned.m16n8k16.row.col.f32.bf16.bf16.f32 "
                 "{%0,%1,%2,%3}, {%4,%5,%6,%7}, {%8,%9}, {%0,%1,%2,%3};"
                 : "+f"(c[0]), "+f"(c[1]), "+f"(c[2]), "+f"(c[3])
                 : "r"(a[0]), "r"(a[1]), "r"(a[2]), "r"(a[3]), "r"(b[0]), "r"(b[1]));
}
#define CP16(dst, src) \
    asm volatile("cp.async.cg.shared.global [%0], [%1], 16;" :: "r"(dst), "l"(src))
#define CP_COMMIT() asm volatile("cp.async.commit_group;" ::: "memory")
#define CP_WAIT1()  asm volatile("cp.async.wait_group 1;" ::: "memory")
#define CP_WAIT0()  asm volatile("cp.async.wait_group 0;" ::: "memory")

__device__ __forceinline__ void split_bf16(float v, __nv_bfloat16& h, __nv_bfloat16& l) {
    h = __float2bfloat16(v);
    l = __float2bfloat16(v - __bfloat162float(h));
}

// ================= transpose + split-convert: in[K,N] -> hi/lo [N,K] =================
__global__ void tconv_kernel(const float* __restrict__ in,
                             __nv_bfloat16* __restrict__ oh,
                             __nv_bfloat16* __restrict__ ol,
                             int K, int N)
{
    __shared__ float t[32][33];
    int n0 = blockIdx.x * 32, k0 = blockIdx.y * 32;
    size_t ib = (size_t)blockIdx.z * K * N;
    int tx = threadIdx.x, ty = threadIdx.y;
#pragma unroll
    for (int j = 0; j < 32; j += 8)
        t[ty + j][tx] = in[ib + (size_t)(k0 + ty + j) * N + n0 + tx];
    __syncthreads();
#pragma unroll
    for (int j = 0; j < 32; j += 8) {
        float v = t[tx][ty + j];
        __nv_bfloat16 h, l;
        split_bf16(v, h, l);
        size_t o = ib + (size_t)(n0 + ty + j) * K + k0 + tx;
        oh[o] = h;
        ol[o] = l;
    }
}

// ================= bf16x3 GEMM, cp.async 3-stage pipeline (unchanged from R7) =================
#define KC 32
#define RST 80
#define A_SZ  (128 * RST)
#define B_SZ  (256 * RST)
#define STG   (2 * A_SZ + 2 * B_SZ)
#define ALO_R A_SZ
#define BHI_R (2 * A_SZ)
#define BLO_R (2 * A_SZ + B_SZ)
#define EROFF (3 * STG)
#define GEMM_SMEM (EROFF + 512)

__global__ void __launch_bounds__(512) bf16x3_gemm_kernel(
    int mode,
    const __nv_bfloat16* __restrict__ Ah, const __nv_bfloat16* __restrict__ Al,
    const __nv_bfloat16* __restrict__ Bh, const __nv_bfloat16* __restrict__ Bl,
    float* __restrict__ C, const float* __restrict__ addsrc, int N, int K)
{
    int e  = blockIdx.z;
    int m0 = blockIdx.y * 128;
    int n0 = blockIdx.x * 256;
    int cnt = 0;
    if (mode != 0) {
        cnt = g_ecnt[e];
        if (m0 >= cnt) return;
        Bh += (size_t)e * N * K;
        Bl += (size_t)e * N * K;
    }
    extern __shared__ char sm[];
    uint32_t sb = smem_u32(sm);
    int tid = threadIdx.x, wid = tid >> 5, l = tid & 31;
    int* erows_s = (int*)(sm + EROFF);
    if (mode != 0 && tid < 128)
        erows_s[tid] = (m0 + tid < cnt) ? g_erows[e * TT + m0 + tid] : 0;
    __syncthreads();

    int arow = tid >> 2, apart = tid & 3;
    size_t aro;
    if (mode == 0)      aro = (size_t)(m0 + arow) * K;
    else if (mode == 1) aro = (size_t)(erows_s[arow] >> 2) * DD;
    else                aro = (size_t)erows_s[arow] * NF;
    const __nv_bfloat16* aph = Ah + aro + apart * 8;
    const __nv_bfloat16* apl = Al + aro + apart * 8;
    uint32_t a_dst = (uint32_t)(arow * RST + apart * 16);

    size_t bo0 = (size_t)(n0 + arow) * K + apart * 8;
    size_t bo1 = (size_t)(n0 + arow + 128) * K + apart * 8;
    uint32_t b_dst0 = (uint32_t)(arow * RST + apart * 16);
    uint32_t b_dst1 = (uint32_t)((arow + 128) * RST + apart * 16);

    int NC = K / KC;

    int wm = wid >> 2, wn = wid & 3;
    int a_r = (l & 7) + ((l >> 3) & 1) * 8, a_c = (l >> 4) * 8;
    int b_r = (l & 7) + (l >> 4) * 8,       b_c = ((l >> 3) & 1) * 8;
    uint32_t aoff = (uint32_t)((wm * 32 + a_r) * RST + a_c * 2);
    uint32_t boff = (uint32_t)(BHI_R + (wn * 64 + b_r) * RST + b_c * 2);

    float acc[2][8][4];
#pragma unroll
    for (int mi = 0; mi < 2; mi++)
#pragma unroll
        for (int ni = 0; ni < 8; ni++)
#pragma unroll
            for (int j = 0; j < 4; j++) acc[mi][ni][j] = 0.f;

#pragma unroll
    for (int p = 0; p < 2; p++) {
        if (p < NC) {
            uint32_t st = sb + p * STG;
            int k0 = p * KC;
            CP16(st + a_dst, aph + k0);
            CP16(st + ALO_R + a_dst, apl + k0);
            CP16(st + BHI_R + b_dst0, Bh + bo0 + k0);
            CP16(st + BHI_R + b_dst1, Bh + bo1 + k0);
            CP16(st + BLO_R + b_dst0, Bl + bo0 + k0);
            CP16(st + BLO_R + b_dst1, Bl + bo1 + k0);
        }
        CP_COMMIT();
    }

    for (int c = 0; c < NC; c++) {
        if (c + 1 < NC) CP_WAIT1(); else CP_WAIT0();
        __syncthreads();
        if (c + 2 < NC) {
            int nc2 = c + 2;
            uint32_t st = sb + (nc2 % 3) * STG;
            int k0 = nc2 * KC;
            CP16(st + a_dst, aph + k0);
            CP16(st + ALO_R + a_dst, apl + k0);
            CP16(st + BHI_R + b_dst0, Bh + bo0 + k0);
            CP16(st + BHI_R + b_dst1, Bh + bo1 + k0);
            CP16(st + BLO_R + b_dst0, Bl + bo0 + k0);
            CP16(st + BLO_R + b_dst1, Bl + bo1 + k0);
        }
        CP_COMMIT();

        uint32_t st = sb + (c % 3) * STG;
#pragma unroll
        for (int kk = 0; kk < 2; kk++) {
            uint32_t bh[4][4], bl4[4][4];
#pragma unroll
            for (int q = 0; q < 4; q++) {
                ldsm4(bh[q],  st + boff + q * (16 * RST) + kk * 32);
                ldsm4(bl4[q], st + boff + B_SZ + q * (16 * RST) + kk * 32);
            }
#pragma unroll
            for (int mi = 0; mi < 2; mi++) {
                uint32_t ah4[4], al4[4];
                ldsm4(ah4, st + aoff + mi * (16 * RST) + kk * 32);
                ldsm4(al4, st + aoff + ALO_R + mi * (16 * RST) + kk * 32);
#pragma unroll
                for (int q = 0; q < 4; q++) {
                    mma16816(acc[mi][q * 2],     ah4, &bh[q][0]);
                    mma16816(acc[mi][q * 2],     ah4, &bl4[q][0]);
                    mma16816(acc[mi][q * 2],     al4, &bh[q][0]);
                    mma16816(acc[mi][q * 2 + 1], ah4, &bh[q][2]);
                    mma16816(acc[mi][q * 2 + 1], ah4, &bl4[q][2]);
                    mma16816(acc[mi][q * 2 + 1], al4, &bh[q][2]);
                }
            }
        }
    }

    int g = l >> 2, tig = l & 3;
#pragma unroll
    for (int mi = 0; mi < 2; mi++) {
        int r0 = wm * 32 + mi * 16 + g;
        int r1 = r0 + 8;
        bool v0 = true, v1 = true;
        size_t ro0 = 0, ro1 = 0;
        float w0 = 0.f, w1 = 0.f;
        if (mode == 0) {
            ro0 = (size_t)(m0 + r0) * N;
            ro1 = (size_t)(m0 + r1) * N;
        } else {
            v0 = (m0 + r0) < cnt;
            v1 = (m0 + r1) < cnt;
            int rowid0 = erows_s[r0], rowid1 = erows_s[r1];
            if (mode == 1) {
                ro0 = (size_t)rowid0 * (2 * NF);
                ro1 = (size_t)rowid1 * (2 * NF);
            } else {
                ro0 = (size_t)(rowid0 >> 2) * DD;
                ro1 = (size_t)(rowid1 >> 2) * DD;
                if (v0) w0 = g_rw[rowid0];
                if (v1) w1 = g_rw[rowid1];
            }
        }
#pragma unroll
        for (int ni = 0; ni < 8; ni++) {
            int cc = n0 + wn * 64 + ni * 8 + tig * 2;
            float* a = acc[mi][ni];
            if (mode == 0) {
                if (addsrc) {
                    float2 s0 = *(const float2*)(addsrc + ro0 + cc);
                    float2 s1 = *(const float2*)(addsrc + ro1 + cc);
                    *(float2*)(C + ro0 + cc) = make_float2(a[0] + s0.x, a[1] + s0.y);
                    *(float2*)(C + ro1 + cc) = make_float2(a[2] + s1.x, a[3] + s1.y);
                } else {
                    *(float2*)(C + ro0 + cc) = make_float2(a[0], a[1]);
                    *(float2*)(C + ro1 + cc) = make_float2(a[2], a[3]);
                }
            } else if (mode == 1) {
                if (v0) *(float2*)(C + ro0 + cc) = make_float2(a[0], a[1]);
                if (v1) *(float2*)(C + ro1 + cc) = make_float2(a[2], a[3]);
            } else {
                if (v0) { atomicAdd(C + ro0 + cc, w0 * a[0]); atomicAdd(C + ro0 + cc + 1, w0 * a[1]); }
                if (v1) { atomicAdd(C + ro1 + cc, w1 * a[2]); atomicAdd(C + ro1 + cc + 1, w1 * a[3]); }
            }
        }
    }
}

// ================= RMSNorm (split-bf16 + optional fp32 out) =================
__global__ void rmsnorm_kernel(const float* __restrict__ x,
                               const float* __restrict__ w,
                               float* __restrict__ ofp,
                               __nv_bfloat16* __restrict__ oh,
                               __nv_bfloat16* __restrict__ ol)
{
    int t = blockIdx.x;
    const float4* xr = (const float4*)(x + (size_t)t * DD);
    const float4* wr = (const float4*)w;
    int tid = threadIdx.x;
    float4 v0 = xr[tid], v1 = xr[tid + 256];
    float ss = v0.x*v0.x + v0.y*v0.y + v0.z*v0.z + v0.w*v0.w
             + v1.x*v1.x + v1.y*v1.y + v1.z*v1.z + v1.w*v1.w;
#pragma unroll
    for (int o = 16; o; o >>= 1) ss += __shfl_xor_sync(0xffffffffu, ss, o);
    __shared__ float red[8];
    if ((tid & 31) == 0) red[tid >> 5] = ss;
    __syncthreads();
    float tot = red[0]+red[1]+red[2]+red[3]+red[4]+red[5]+red[6]+red[7];
    float r = rsqrtf(tot / (float)DD + 1e-6f);
    float4 w0 = wr[tid], w1 = wr[tid + 256];
    float4 o0, o1;
    o0.x = v0.x*r*w0.x; o0.y = v0.y*r*w0.y; o0.z = v0.z*r*w0.z; o0.w = v0.w*r*w0.w;
    o1.x = v1.x*r*w1.x; o1.y = v1.y*r*w1.y; o1.z = v1.z*r*w1.z; o1.w = v1.w*r*w1.w;
    if (ofp) {
        float4* orow = (float4*)(ofp + (size_t)t * DD);
        orow[tid] = o0; orow[tid + 256] = o1;
    }
    __nv_bfloat16 h[8], lo[8];
    split_bf16(o0.x, h[0], lo[0]); split_bf16(o0.y, h[1], lo[1]);
    split_bf16(o0.z, h[2], lo[2]); split_bf16(o0.w, h[3], lo[3]);
    split_bf16(o1.x, h[4], lo[4]); split_bf16(o1.y, h[5], lo[5]);
    split_bf16(o1.z, h[6], lo[6]); split_bf16(o1.w, h[7], lo[7]);
    uint2* ohr = (uint2*)(oh + (size_t)t * DD);
    uint2* olr = (uint2*)(ol + (size_t)t * DD);
    ohr[tid]       = make_uint2(pack2bf(h[0], h[1]),  pack2bf(h[2], h[3]));
    ohr[tid + 256] = make_uint2(pack2bf(h[4], h[5]),  pack2bf(h[6], h[7]));
    olr[tid]       = make_uint2(pack2bf(lo[0], lo[1]), pack2bf(lo[2], lo[3]));
    olr[tid + 256] = make_uint2(pack2bf(lo[4], lo[5]), pack2bf(lo[6], lo[7]));
}

// ================= per-head RMSNorm + RoPE + split (q/k) ; split-only (v) =================
__global__ void normrope_kernel(const float* __restrict__ cosb,
                                const float* __restrict__ sinb,
                                const float* __restrict__ qnw,
                                const float* __restrict__ knw)
{
    int t = blockIdx.x;
    int head = blockIdx.y;      // 0..15 q, 16..19 k, 20..23 v
    int h = threadIdx.x;
    if (head >= 20) {
        int kvh = head - 20;
        float v = g_qkv[(size_t)t * QKVW + VOFF + kvh * HDIM + h];
        __nv_bfloat16 hh, ll;
        split_bf16(v, hh, ll);
        size_t o = ((size_t)t * NKV + kvh) * HDIM + h;
        g_v_h[o] = hh; g_v_l[o] = ll;
        return;
    }
    const float* src;
    const float* nw;
    if (head < NQ) { src = g_qkv + (size_t)t * QKVW + head * HDIM;               nw = qnw; }
    else           { src = g_qkv + (size_t)t * QKVW + KOFF + (head - NQ) * HDIM; nw = knw; }
    float v = src[h];
    float ss = v * v;
#pragma unroll
    for (int o = 16; o; o >>= 1) ss += __shfl_xor_sync(0xffffffffu, ss, o);
    __shared__ float red[4];
    __shared__ float xs[128];
    if ((h & 31) == 0) red[h >> 5] = ss;
    __syncthreads();
    float tot = red[0] + red[1] + red[2] + red[3];
    float xn = v * rsqrtf(tot / (float)HDIM + 1e-6f) * nw[h];
    xs[h] = xn;
    __syncthreads();
    float c = cosb[(size_t)t * HDIM + h];
    float s = sinb[(size_t)t * HDIM + h];
    float other = (h < 64) ? xs[h + 64] : xs[h - 64];
    float outv = (h < 64) ? (xn * c - other * s) : (xn * c + other * s);
    __nv_bfloat16 hh, ll;
    split_bf16(outv, hh, ll);
    if (head < NQ) {
        size_t o = ((size_t)t * NQ + head) * HDIM + h;
        g_q_h[o] = hh; g_q_l[o] = ll;
    } else {
        size_t o = ((size_t)t * NKV + (head - NQ)) * HDIM + h;
        g_k_h[o] = hh; g_k_l[o] = ll;
    }
}

// ================= flash attention, bf16x3 HMMA =================
// CTA: 64 q-rows x 1 head, 4 warps (warp = m16). K/V 64-row tiles staged hi/lo.
#define AT_RST  272                  // smem row stride bytes (128 bf16 + pad)
#define AT_TILE (64 * AT_RST)        // 17408
#define AT_QH 0
#define AT_QL (1 * AT_TILE)
#define AT_KH (2 * AT_TILE)
#define AT_KL (3 * AT_TILE)
#define AT_VH (4 * AT_TILE)
#define AT_VL (5 * AT_TILE)
#define AT_SMEM (6 * AT_TILE)        // 104448

__device__ __forceinline__ void attn_issue_kv(uint32_t sb, int j0, int kvh,
                                              int srow, int spart)
{
    size_t base = ((size_t)(j0 + srow) * NKV + kvh) * HDIM + spart * 64;
    uint32_t d = (uint32_t)(srow * AT_RST + spart * 128);
#pragma unroll
    for (int i = 0; i < 8; i++) {
        CP16(sb + AT_KH + d + i * 16, g_k_h + base + i * 8);
        CP16(sb + AT_KL + d + i * 16, g_k_l + base + i * 8);
        CP16(sb + AT_VH + d + i * 16, g_v_h + base + i * 8);
        CP16(sb + AT_VL + d + i * 16, g_v_l + base + i * 8);
    }
}

__global__ void __launch_bounds__(128) attn_kernel()
{
    extern __shared__ char sm[];
    uint32_t sb = smem_u32(sm);
    int m0 = blockIdx.x * 64;
    int head = blockIdx.y;
    int kvh = head >> 2;
    int tid = threadIdx.x, wid = tid >> 5, l = tid & 31;
    const float scale = 0.08838834764831843f;

    // staging mapping: 2 threads per row
    int srow = tid >> 1, spart = tid & 1;
    {   // Q tile (resident)
        size_t qb = ((size_t)(m0 + srow) * NQ + head) * HDIM + spart * 64;
        uint32_t d = (uint32_t)(srow * AT_RST + spart * 128);
#pragma unroll
        for (int i = 0; i < 8; i++) {
            CP16(sb + AT_QH + d + i * 16, g_q_h + qb + i * 8);
            CP16(sb + AT_QL + d + i * 16, g_q_l + qb + i * 8);
        }
    }
    attn_issue_kv(sb, 0, kvh, srow, spart);
    CP_COMMIT();

    // fragment address components
    int a_r = (l & 7) + ((l >> 3) & 1) * 8;
    int a_c = (l >> 4) * 8;
    int b_r = (l & 7) + (l >> 4) * 8;
    int b_c = ((l >> 3) & 1) * 8;

    float o[16][4];
#pragma unroll
    for (int nd = 0; nd < 16; nd++)
#pragma unroll
        for (int j = 0; j < 4; j++) o[nd][j] = 0.f;
    float m_i0 = -1e30f, m_i1 = -1e30f, l0 = 0.f, l1 = 0.f;

    int njt = blockIdx.x + 1;
    for (int jt = 0; jt < njt; jt++) {
        CP_WAIT0();
        __syncthreads();

        // ---- S = Q K^T (bf16x3) ----
        float s[8][4];
#pragma unroll
        for (int ni = 0; ni < 8; ni++)
#pragma unroll
            for (int j = 0; j < 4; j++) s[ni][j] = 0.f;
#pragma unroll
        for (int ks = 0; ks < 8; ks++) {
            uint32_t qh4[4], ql4[4];
            uint32_t qa = sb + (uint32_t)((wid * 16 + a_r) * AT_RST + (ks * 16 + a_c) * 2);
            ldsm4(qh4, qa + AT_QH);
            ldsm4(ql4, qa + AT_QL);
#pragma unroll
            for (int q2 = 0; q2 < 4; q2++) {
                uint32_t kh4[4], kl4[4];
                uint32_t ka = sb + (uint32_t)((q2 * 16 + b_r) * AT_RST + (ks * 16 + b_c) * 2);
                ldsm4(kh4, ka + AT_KH);
                ldsm4(kl4, ka + AT_KL);
                mma16816(s[q2 * 2],     qh4, &kh4[0]);
                mma16816(s[q2 * 2],     qh4, &kl4[0]);
                mma16816(s[q2 * 2],     ql4, &kh4[0]);
                mma16816(s[q2 * 2 + 1], qh4, &kh4[2]);
                mma16816(s[q2 * 2 + 1], qh4, &kl4[2]);
                mma16816(s[q2 * 2 + 1], ql4, &kh4[2]);
            }
        }
        // scale
#pragma unroll
        for (int ni = 0; ni < 8; ni++)
#pragma unroll
            for (int j = 0; j < 4; j++) s[ni][j] *= scale;
        // causal mask (diagonal tile only)
        if (jt == njt - 1) {
            int rA = wid * 16 + (l >> 2), rB = rA + 8;
#pragma unroll
            for (int ni = 0; ni < 8; ni++) {
                int c0 = ni * 8 + 2 * (l & 3), c1 = c0 + 1;
                if (c0 > rA) s[ni][0] = -1e30f;
                if (c1 > rA) s[ni][1] = -1e30f;
                if (c0 > rB) s[ni][2] = -1e30f;
                if (c1 > rB) s[ni][3] = -1e30f;
            }
        }
        // row max
        float mt0 = -1e30f, mt1 = -1e30f;
#pragma unroll
        for (int ni = 0; ni < 8; ni++) {
            mt0 = fmaxf(mt0, fmaxf(s[ni][0], s[ni][1]));
            mt1 = fmaxf(mt1, fmaxf(s[ni][2], s[ni][3]));
        }
        mt0 = fmaxf(mt0, __shfl_xor_sync(0xffffffffu, mt0, 1));
        mt0 = fmaxf(mt0, __shfl_xor_sync(0xffffffffu, mt0, 2));
        mt1 = fmaxf(mt1, __shfl_xor_sync(0xffffffffu, mt1, 1));
        mt1 = fmaxf(mt1, __shfl_xor_sync(0xffffffffu, mt1, 2));
        float mn0 = fmaxf(m_i0, mt0), mn1 = fmaxf(m_i1, mt1);
        float c0 = __expf(m_i0 - mn0), c1 = __expf(m_i1 - mn1);
        l0 *= c0; l1 *= c1;
#pragma unroll
        for (int nd = 0; nd < 16; nd++) {
            o[nd][0] *= c0; o[nd][1] *= c0; o[nd][2] *= c1; o[nd][3] *= c1;
        }
        m_i0 = mn0; m_i1 = mn1;
        // p = exp(s - m), row sums, pack into A-frag halves
        float rs0 = 0.f, rs1 = 0.f;
        uint32_t pha[16], pla[16];
#pragma unroll
        for (int ni = 0; ni < 8; ni++) {
            float p0 = __expf(s[ni][0] - mn0), p1 = __expf(s[ni][1] - mn0);
            float p2 = __expf(s[ni][2] - mn1), p3 = __expf(s[ni][3] - mn1);
            rs0 += p0 + p1; rs1 += p2 + p3;
            __nv_bfloat16 h0, l0b, h1, l1b, h2, l2b, h3, l3b;
            split_bf16(p0, h0, l0b); split_bf16(p1, h1, l1b);
            split_bf16(p2, h2, l2b); split_bf16(p3, h3, l3b);
            pha[2 * ni]     = pack2bf(h0, h1);
            pha[2 * ni + 1] = pack2bf(h2, h3);
            pla[2 * ni]     = pack2bf(l0b, l1b);
            pla[2 * ni + 1] = pack2bf(l2b, l3b);
        }
        rs0 += __shfl_xor_sync(0xffffffffu, rs0, 1);
        rs0 += __shfl_xor_sync(0xffffffffu, rs0, 2);
        rs1 += __shfl_xor_sync(0xffffffffu, rs1, 1);
        rs1 += __shfl_xor_sync(0xffffffffu, rs1, 2);
        l0 += rs0; l1 += rs1;

        // ---- O += P V (bf16x3, V via ldsm.trans) ----
#pragma unroll
        for (int ks = 0; ks < 4; ks++) {
            const uint32_t* ph = &pha[4 * ks];
            const uint32_t* pl = &pla[4 * ks];
#pragma unroll
            for (int dg = 0; dg < 8; dg++) {
                uint32_t vh4[4], vl4[4];
                uint32_t va = sb + (uint32_t)((ks * 16 + a_r) * AT_RST + (dg * 16 + a_c) * 2);
                ldsm4t(vh4, va + AT_VH);
                ldsm4t(vl4, va + AT_VL);
                mma16816(o[2 * dg],     ph, &vh4[0]);
                mma16816(o[2 * dg],     pl, &vh4[0]);
                mma16816(o[2 * dg],     ph, &vl4[0]);
                mma16816(o[2 * dg + 1], ph, &vh4[2]);
                mma16816(o[2 * dg + 1], pl, &vh4[2]);
                mma16816(o[2 * dg + 1], ph, &vl4[2]);
            }
        }
        __syncthreads();
        if (jt + 1 < njt) attn_issue_kv(sb, (jt + 1) * 64, kvh, srow, spart);
        CP_COMMIT();
    }

    // ---- epilogue: normalize, split, store ----
    float inv0 = 1.f / l0, inv1 = 1.f / l1;
    int rA = m0 + wid * 16 + (l >> 2);
    int rB = rA + 8;
#pragma unroll
    for (int nd = 0; nd < 16; nd++) {
        int d = nd * 8 + 2 * (l & 3);
        float v0 = o[nd][0] * inv0, v1 = o[nd][1] * inv0;
        float v2 = o[nd][2] * inv1, v3 = o[nd][3] * inv1;
        __nv_bfloat16 h0, lo0, h1, lo1, h2, lo2, h3, lo3;
        split_bf16(v0, h0, lo0); split_bf16(v1, h1, lo1);
        split_bf16(v2, h2, lo2); split_bf16(v3, h3, lo3);
        size_t oA = (size_t)rA * DD + head * HDIM + d;
        size_t oB = (size_t)rB * DD + head * HDIM + d;
        *(uint32_t*)(g_attn_h + oA) = pack2bf(h0, h1);
        *(uint32_t*)(g_attn_l + oA) = pack2bf(lo0, lo1);
        *(uint32_t*)(g_attn_h + oB) = pack2bf(h2, h3);
        *(uint32_t*)(g_attn_l + oB) = pack2bf(lo2, lo3);
    }
}

// ================= routing =================
__global__ void zero_cnt_kernel() { if (threadIdx.x < NE) g_ecnt[threadIdx.x] = 0; }

__global__ void route_kernel(const float* __restrict__ gate_w)
{
    int t = blockIdx.x;
    int tid = threadIdx.x;
    const float* x = g_h2 + (size_t)t * DD;
    float acc[NE];
#pragma unroll
    for (int e = 0; e < NE; e++) acc[e] = 0.f;
    for (int d = tid; d < DD; d += 128) {
        float xv = x[d];
        const float* gw = gate_w + (size_t)d * NE;
#pragma unroll
        for (int e = 0; e < NE; e++) acc[e] += xv * gw[e];
    }
    __shared__ float s[NE * 128];
#pragma unroll
    for (int e = 0; e < NE; e++) s[e * 128 + tid] = acc[e];
    __syncthreads();
    __shared__ float logits[NE];
    if (tid < NE) {
        float sum = 0.f;
        for (int i = 0; i < 128; i++) sum += s[tid * 128 + i];
        logits[tid] = sum;
    }
    __syncthreads();
    if (tid == 0) {
        float mx = -1e30f;
        for (int e = 0; e < NE; e++) mx = fmaxf(mx, logits[e]);
        float p[NE], Z = 0.f;
        for (int e = 0; e < NE; e++) { p[e] = expf(logits[e] - mx); Z += p[e]; }
        for (int e = 0; e < NE; e++) p[e] /= Z;
        int idx[TOPK]; float val[TOPK]; bool used[NE] = {};
        float wsum = 0.f;
        for (int k = 0; k < TOPK; k++) {
            int best = -1; float bv = -1.f;
            for (int e = 0; e < NE; e++)
                if (!used[e] && p[e] > bv) { bv = p[e]; best = e; }
            used[best] = true; idx[k] = best; val[k] = bv; wsum += bv;
        }
        for (int k = 0; k < TOPK; k++) {
            int rowid = t * TOPK + k;
            g_rw[rowid] = val[k] / wsum;
            int e = idx[k];
            int pos = atomicAdd(&g_ecnt[e], 1);
            g_erows[e * TT + pos] = rowid;
        }
    }
}

__global__ void silu_kernel()
{
    size_t i = (size_t)blockIdx.x * 256 + threadIdx.x;
    int r = (int)(i >> 10);
    int f = (int)(i & 1023);
    float g = g_gu[(size_t)r * (2 * NF) + f];
    float u = g_gu[(size_t)r * (2 * NF) + NF + f];
    float v = u * (g / (1.f + __expf(-g)));
    __nv_bfloat16 h, lo;
    split_bf16(v, h, lo);
    g_gated_h[i] = h;
    g_gated_l[i] = lo;
}

__global__ void copy_out_kernel(float* __restrict__ out)
{
    size_t i = (size_t)blockIdx.x * 256 + threadIdx.x;
    ((float4*)out)[i] = ((const float4*)g_hmid)[i];
}

// ================= launch =================
extern "C" void kernel_launch(void* const* d_in, const int* in_sizes, int n_in,
                              void* d_out, int out_size)
{
    const float* hidden  = (const float*)d_in[0];
    const float* cosb    = (const float*)d_in[1];
    const float* sinb    = (const float*)d_in[2];
    const float* in_ln   = (const float*)d_in[4];
    const float* post_ln = (const float*)d_in[5];
    const float* q_w     = (const float*)d_in[6];
    const float* k_w     = (const float*)d_in[7];
    const float* v_w     = (const float*)d_in[8];
    const float* o_w     = (const float*)d_in[9];
    const float* q_nw    = (const float*)d_in[10];
    const float* k_nw    = (const float*)d_in[11];
    const float* gate_w  = (const float*)d_in[12];
    const float* gup_w   = (const float*)d_in[13];
    const float* down_w  = (const float*)d_in[14];
    float* out = (float*)d_out;

    float *qkv, *hmid, *h2, *gu;
    __nv_bfloat16 *hn_h, *hn_l, *attn_h, *attn_l, *h2_h, *h2_l, *gated_h, *gated_l;
    __nv_bfloat16 *qkvT_h, *qkvT_l, *owT_h, *owT_l, *guT_h, *guT_l, *dwT_h, *dwT_l;
    cudaGetSymbolAddress((void**)&qkv,  g_qkv);
    cudaGetSymbolAddress((void**)&hmid, g_hmid);
    cudaGetSymbolAddress((void**)&h2,   g_h2);
    cudaGetSymbolAddress((void**)&gu,   g_gu);
    cudaGetSymbolAddress((void**)&hn_h, g_hn_h);
    cudaGetSymbolAddress((void**)&hn_l, g_hn_l);
    cudaGetSymbolAddress((void**)&attn_h, g_attn_h);
    cudaGetSymbolAddress((void**)&attn_l, g_attn_l);
    cudaGetSymbolAddress((void**)&h2_h, g_h2_h);
    cudaGetSymbolAddress((void**)&h2_l, g_h2_l);
    cudaGetSymbolAddress((void**)&gated_h, g_gated_h);
    cudaGetSymbolAddress((void**)&gated_l, g_gated_l);
    cudaGetSymbolAddress((void**)&qkvT_h, g_qkvT_h);
    cudaGetSymbolAddress((void**)&qkvT_l, g_qkvT_l);
    cudaGetSymbolAddress((void**)&owT_h,  g_owT_h);
    cudaGetSymbolAddress((void**)&owT_l,  g_owT_l);
    cudaGetSymbolAddress((void**)&guT_h,  g_guT_h);
    cudaGetSymbolAddress((void**)&guT_l,  g_guT_l);
    cudaGetSymbolAddress((void**)&dwT_h,  g_dwT_h);
    cudaGetSymbolAddress((void**)&dwT_l,  g_dwT_l);

    cudaFuncSetAttribute(bf16x3_gemm_kernel, cudaFuncAttributeMaxDynamicSharedMemorySize, GEMM_SMEM);
    cudaFuncSetAttribute(attn_kernel, cudaFuncAttributeMaxDynamicSharedMemorySize, AT_SMEM);

    dim3 tb(32, 8);
    tconv_kernel<<<dim3(64, 64, 1),  tb>>>(q_w,  qkvT_h,                     qkvT_l,                     DD, 2048);
    tconv_kernel<<<dim3(16, 64, 1),  tb>>>(k_w,  qkvT_h + (size_t)KOFF * DD, qkvT_l + (size_t)KOFF * DD, DD, 512);
    tconv_kernel<<<dim3(16, 64, 1),  tb>>>(v_w,  qkvT_h + (size_t)VOFF * DD, qkvT_l + (size_t)VOFF * DD, DD, 512);
    tconv_kernel<<<dim3(64, 64, 1),  tb>>>(o_w,  owT_h, owT_l, DD, 2048);
    tconv_kernel<<<dim3(64, 64, NE), tb>>>(gup_w, guT_h, guT_l, DD, 2048);
    tconv_kernel<<<dim3(64, 32, NE), tb>>>(down_w, dwT_h, dwT_l, NF, 2048);

    // 1. pre-attn rmsnorm (split-bf16 out)
    rmsnorm_kernel<<<TT, 256>>>(hidden, in_ln, nullptr, hn_h, hn_l);
    // 2. fused QKV projection (N=3072)
    bf16x3_gemm_kernel<<<dim3(QKVW / 256, TT / 128), 512, GEMM_SMEM>>>(
        0, hn_h, hn_l, qkvT_h, qkvT_l, qkv, nullptr, QKVW, DD);
    // 3. per-head norm + rope + split (q,k) / split (v)
    normrope_kernel<<<dim3(TT, NQ + NKV + NKV), 128>>>(cosb, sinb, q_nw, k_nw);
    // 4. attention (bf16x3 HMMA flash)
    attn_kernel<<<dim3(TT / 64, NQ), 128, AT_SMEM>>>();
    // 5. O projection + residual
    bf16x3_gemm_kernel<<<dim3(DD / 256, TT / 128), 512, GEMM_SMEM>>>(
        0, attn_h, attn_l, owT_h, owT_l, hmid, hidden, DD, DD);
    // 6. post-attn rmsnorm
    rmsnorm_kernel<<<TT, 256>>>(hmid, post_ln, h2, h2_h, h2_l);
    // 7. routing
    zero_cnt_kernel<<<1, 32>>>();
    route_kernel<<<TT, 128>>>(gate_w);
    // 8. init output with residual, then sparse expert GEMMs
    copy_out_kernel<<<TT * DD / 4 / 256, 256>>>(out);
    bf16x3_gemm_kernel<<<dim3((2 * NF) / 256, 16, NE), 512, GEMM_SMEM>>>(
        1, h2_h, h2_l, guT_h, guT_l, gu, nullptr, 2 * NF, DD);
    silu_kernel<<<(TT * TOPK * NF) / 256, 256>>>();
    bf16x3_gemm_kernel<<<dim3(DD / 256, 16, NE), 512, GEMM_SMEM>>>(
        2, gated_h, gated_l, dwT_h, dwT_l, out, nullptr, DD, NF);
}